// round 4
// baseline (speedup 1.0000x reference)
#include <cuda_runtime.h>
#include <math.h>

#define EDIM 1024
#define TLEN 1024
#define BATCH 4
#define NHEAD 16
#define HDIM 64
#define MROWS (BATCH * TLEN)   // 4096

typedef unsigned long long ull;

// ---------------- packed f32x2 helpers (sm_103a) ----------------
__device__ __forceinline__ ull ffma2(ull a, ull b, ull c) {
    ull d;
    asm("fma.rn.f32x2 %0, %1, %2, %3;" : "=l"(d) : "l"(a), "l"(b), "l"(c));
    return d;
}
__device__ __forceinline__ ull fmul2(ull a, ull b) {
    ull d;
    asm("mul.rn.f32x2 %0, %1, %2;" : "=l"(d) : "l"(a), "l"(b));
    return d;
}
__device__ __forceinline__ ull pack2(float lo, float hi) {
    ull d;
    asm("mov.b64 %0, {%1, %2};" : "=l"(d) : "f"(lo), "f"(hi));
    return d;
}
__device__ __forceinline__ float2 unpack2(ull v) {
    float2 f;
    asm("mov.b64 {%0, %1}, %2;" : "=f"(f.x), "=f"(f.y) : "l"(v));
    return f;
}

// ---------------- scratch (device globals: no runtime allocation) ----------
__device__ float g_q[(size_t)MROWS * EDIM];
__device__ float g_k[(size_t)MROWS * EDIM];
__device__ float g_v[(size_t)MROWS * EDIM];
__device__ float g_att[(size_t)MROWS * EDIM];

// ============================================================================
// GEMM: C[M,N] = A[M,K] @ W[N,K]^T + bias, FFMA2 inner product, reg prefetch.
// BM=BN=128, BK=16, 256 threads, 8x8 micro-tile (acc as 8x4 f32x2 pairs on n).
// ============================================================================
__global__ __launch_bounds__(256, 2) void gemm_nt_bias(
    const float* __restrict__ A, const float* __restrict__ W,
    const float* __restrict__ bias, float* __restrict__ C,
    int N, int K)
{
    __shared__ float As[16][132];
    __shared__ float Ws[16][132];

    const int t  = threadIdx.x;
    const int tx = t & 15;
    const int ty = t >> 4;
    const int n0 = blockIdx.x * 128;
    const int m0 = blockIdx.y * 128;

    const int r0  = t >> 2;          // 0..63
    const int r1  = r0 + 64;         // 64..127
    const int kq  = t & 3;           // float4 index along K

    const float* Ap0 = &A[(m0 + r0) * K + kq * 4];
    const float* Ap1 = &A[(m0 + r1) * K + kq * 4];
    const float* Wp0 = &W[(n0 + r0) * K + kq * 4];
    const float* Wp1 = &W[(n0 + r1) * K + kq * 4];

    ull acc2[8][4];
#pragma unroll
    for (int i = 0; i < 8; i++)
#pragma unroll
        for (int j = 0; j < 4; j++) acc2[i][j] = 0ULL;

    float4 a0 = *(const float4*)Ap0;
    float4 a1 = *(const float4*)Ap1;
    float4 w0 = *(const float4*)Wp0;
    float4 w1 = *(const float4*)Wp1;

    for (int k0 = 0; k0 < K; k0 += 16) {
        if (k0) __syncthreads();
        As[kq * 4 + 0][r0] = a0.x; As[kq * 4 + 1][r0] = a0.y;
        As[kq * 4 + 2][r0] = a0.z; As[kq * 4 + 3][r0] = a0.w;
        As[kq * 4 + 0][r1] = a1.x; As[kq * 4 + 1][r1] = a1.y;
        As[kq * 4 + 2][r1] = a1.z; As[kq * 4 + 3][r1] = a1.w;
        Ws[kq * 4 + 0][r0] = w0.x; Ws[kq * 4 + 1][r0] = w0.y;
        Ws[kq * 4 + 2][r0] = w0.z; Ws[kq * 4 + 3][r0] = w0.w;
        Ws[kq * 4 + 0][r1] = w1.x; Ws[kq * 4 + 1][r1] = w1.y;
        Ws[kq * 4 + 2][r1] = w1.z; Ws[kq * 4 + 3][r1] = w1.w;
        __syncthreads();

        if (k0 + 16 < K) {
            a0 = *(const float4*)(Ap0 + k0 + 16);
            a1 = *(const float4*)(Ap1 + k0 + 16);
            w0 = *(const float4*)(Wp0 + k0 + 16);
            w1 = *(const float4*)(Wp1 + k0 + 16);
        }

#pragma unroll
        for (int k = 0; k < 16; k++) {
            float4 aa = *(const float4*)&As[k][ty * 8];
            float4 ab = *(const float4*)&As[k][ty * 8 + 4];
            ulonglong2 wva = *(const ulonglong2*)&Ws[k][tx * 8];
            ulonglong2 wvb = *(const ulonglong2*)&Ws[k][tx * 8 + 4];
            ull wp[4] = {wva.x, wva.y, wvb.x, wvb.y};
            ull ad[8];
            ad[0] = pack2(aa.x, aa.x); ad[1] = pack2(aa.y, aa.y);
            ad[2] = pack2(aa.z, aa.z); ad[3] = pack2(aa.w, aa.w);
            ad[4] = pack2(ab.x, ab.x); ad[5] = pack2(ab.y, ab.y);
            ad[6] = pack2(ab.z, ab.z); ad[7] = pack2(ab.w, ab.w);
#pragma unroll
            for (int i = 0; i < 8; i++)
#pragma unroll
                for (int j = 0; j < 4; j++)
                    acc2[i][j] = ffma2(ad[i], wp[j], acc2[i][j]);
        }
    }

    float bb[8];
    *(float4*)&bb[0] = *(const float4*)&bias[n0 + tx * 8];
    *(float4*)&bb[4] = *(const float4*)&bias[n0 + tx * 8 + 4];

#pragma unroll
    for (int i = 0; i < 8; i++) {
        float2 c0 = unpack2(acc2[i][0]);
        float2 c1 = unpack2(acc2[i][1]);
        float2 c2 = unpack2(acc2[i][2]);
        float2 c3 = unpack2(acc2[i][3]);
        float4 o0, o1;
        o0.x = c0.x + bb[0]; o0.y = c0.y + bb[1];
        o0.z = c1.x + bb[2]; o0.w = c1.y + bb[3];
        o1.x = c2.x + bb[4]; o1.y = c2.y + bb[5];
        o1.z = c3.x + bb[6]; o1.w = c3.y + bb[7];
        float* crow = &C[(m0 + ty * 8 + i) * N + n0 + tx * 8];
        *(float4*)&crow[0] = o0;
        *(float4*)&crow[4] = o1;
    }
}

// ============================================================================
// Fused flash attention: BQ=BK=128, 256 threads.
// S: 8x8 micro (q dup'd, k natural pairs). PV: 4pairs(q) x 4(d), V duplicated
// in smem so no packs in the PV hot loop. Softmax: S in registers, row stats
// via 16-wide smem reduction, P written transposed.
// smem (floats):
//   Qs[64][132] d-major (scaled 1/8)      @ 0
//   Ks[64][132] d-major                   @ 8448
//   Vsd[128][136] k-major, each v twice   @ 16896
//   Ps[128][132]  (P[k][q])               @ 34304
//   red[128][17]                          @ 51200
//   smM/smL/smA [128] each                @ 53376/53504/53632
// ============================================================================
#define ATTN_SMEM_FLOATS 53760
#define ATTN_SMEM_BYTES (ATTN_SMEM_FLOATS * 4)

__global__ __launch_bounds__(256) void attn_kernel(const int* __restrict__ mask)
{
    extern __shared__ float sm[];
    float* Qs  = sm;
    float* Ks  = sm + 8448;
    float* Vsd = sm + 16896;
    float* Ps  = sm + 34304;
    float* red = sm + 51200;
    float* smM = sm + 53376;
    float* smL = sm + 53504;
    float* smA = sm + 53632;

    const int t  = threadIdx.x;
    const int tx = t & 15;
    const int ty = t >> 4;
    const int q0 = blockIdx.x * 128;
    const int bh = blockIdx.y;
    const int b  = bh >> 4;
    const int h  = bh & 15;
    const int hofs = h * HDIM;

    // Q tile load, transposed + pre-scaled by 1/8
#pragma unroll
    for (int p = 0; p < 8; p++) {
        int id  = t + p * 256;
        int row = id >> 4;
        int d4  = id & 15;
        float4 qv = *(const float4*)&g_q[(b * TLEN + q0 + row) * EDIM + hofs + d4 * 4];
        Qs[(d4 * 4 + 0) * 132 + row] = qv.x * 0.125f;
        Qs[(d4 * 4 + 1) * 132 + row] = qv.y * 0.125f;
        Qs[(d4 * 4 + 2) * 132 + row] = qv.z * 0.125f;
        Qs[(d4 * 4 + 3) * 132 + row] = qv.w * 0.125f;
    }
    if (t < 128) { smM[t] = -1e30f; smL[t] = 0.0f; }

    ull o2[4][4];
#pragma unroll
    for (int i = 0; i < 4; i++)
#pragma unroll
        for (int j = 0; j < 4; j++) o2[i][j] = 0ULL;

    __syncthreads();

    for (int kt = 0; kt < TLEN / 128; kt++) {
        // ---- load K (transposed) and V (duplicated) ----
#pragma unroll
        for (int p = 0; p < 8; p++) {
            int id  = t + p * 256;
            int row = id >> 4;
            int d4  = id & 15;
            const float* base = &g_k[(b * TLEN + kt * 128 + row) * EDIM + hofs + d4 * 4];
            float4 kv = *(const float4*)base;
            Ks[(d4 * 4 + 0) * 132 + row] = kv.x;
            Ks[(d4 * 4 + 1) * 132 + row] = kv.y;
            Ks[(d4 * 4 + 2) * 132 + row] = kv.z;
            Ks[(d4 * 4 + 3) * 132 + row] = kv.w;
            float4 vv = *(const float4*)&g_v[(b * TLEN + kt * 128 + row) * EDIM + hofs + d4 * 4];
            float4 e0 = make_float4(vv.x, vv.x, vv.y, vv.y);
            float4 e1 = make_float4(vv.z, vv.z, vv.w, vv.w);
            *(float4*)&Vsd[row * 136 + d4 * 8]     = e0;
            *(float4*)&Vsd[row * 136 + d4 * 8 + 4] = e1;
        }
        __syncthreads();

        // ---- S = Q*K^T : s2[i (q row)][jp (k pair)] ----
        ull s2[8][4];
#pragma unroll
        for (int i = 0; i < 8; i++)
#pragma unroll
            for (int j = 0; j < 4; j++) s2[i][j] = 0ULL;

#pragma unroll 8
        for (int d = 0; d < 64; d++) {
            float4 qa = *(const float4*)&Qs[d * 132 + ty * 8];
            float4 qb = *(const float4*)&Qs[d * 132 + ty * 8 + 4];
            ulonglong2 kva = *(const ulonglong2*)&Ks[d * 132 + tx * 8];
            ulonglong2 kvb = *(const ulonglong2*)&Ks[d * 132 + tx * 8 + 4];
            ull kp[4] = {kva.x, kva.y, kvb.x, kvb.y};
            ull qd[8];
            qd[0] = pack2(qa.x, qa.x); qd[1] = pack2(qa.y, qa.y);
            qd[2] = pack2(qa.z, qa.z); qd[3] = pack2(qa.w, qa.w);
            qd[4] = pack2(qb.x, qb.x); qd[5] = pack2(qb.y, qb.y);
            qd[6] = pack2(qb.z, qb.z); qd[7] = pack2(qb.w, qb.w);
#pragma unroll
            for (int i = 0; i < 8; i++)
#pragma unroll
                for (int j = 0; j < 4; j++)
                    s2[i][j] = ffma2(qd[i], kp[j], s2[i][j]);
        }

        // ---- mask + per-thread row max ----
#pragma unroll
        for (int i = 0; i < 8; i++) {
            int qg = q0 + ty * 8 + i;
            const int* mrow = &mask[(b * TLEN + qg) * TLEN + kt * 128 + tx * 8];
            int4 m0 = *(const int4*)mrow;
            int4 m1 = *(const int4*)(mrow + 4);
            float2 f0 = unpack2(s2[i][0]);
            float2 f1 = unpack2(s2[i][1]);
            float2 f2 = unpack2(s2[i][2]);
            float2 f3 = unpack2(s2[i][3]);
            f0.x = (m0.x == 0) ? -1.0e9f : f0.x;
            f0.y = (m0.y == 0) ? -1.0e9f : f0.y;
            f1.x = (m0.z == 0) ? -1.0e9f : f1.x;
            f1.y = (m0.w == 0) ? -1.0e9f : f1.y;
            f2.x = (m1.x == 0) ? -1.0e9f : f2.x;
            f2.y = (m1.y == 0) ? -1.0e9f : f2.y;
            f3.x = (m1.z == 0) ? -1.0e9f : f3.x;
            f3.y = (m1.w == 0) ? -1.0e9f : f3.y;
            s2[i][0] = pack2(f0.x, f0.y);
            s2[i][1] = pack2(f1.x, f1.y);
            s2[i][2] = pack2(f2.x, f2.y);
            s2[i][3] = pack2(f3.x, f3.y);
            float lm = fmaxf(fmaxf(fmaxf(f0.x, f0.y), fmaxf(f1.x, f1.y)),
                             fmaxf(fmaxf(f2.x, f2.y), fmaxf(f3.x, f3.y)));
            red[(ty * 8 + i) * 17 + tx] = lm;
        }
        __syncthreads();

        // ---- row stats (max, alpha) ----
        if (t < 128) {
            float rm = -1e30f;
#pragma unroll
            for (int c = 0; c < 16; c++) rm = fmaxf(rm, red[t * 17 + c]);
            float mOld = smM[t];
            float mNew = fmaxf(mOld, rm);
            smA[t] = __expf(mOld - mNew);
            smM[t] = mNew;
        }
        __syncthreads();

        // ---- P = exp(S - m); write transposed Ps[k][q]; partial row sums ----
        float mN[8], psum[8];
#pragma unroll
        for (int i = 0; i < 8; i++) { mN[i] = smM[ty * 8 + i]; psum[i] = 0.0f; }
#pragma unroll
        for (int j = 0; j < 8; j++) {
            float pv[8];
#pragma unroll
            for (int i = 0; i < 8; i++) {
                float2 f = unpack2(s2[i][j >> 1]);
                float sval = (j & 1) ? f.y : f.x;
                float p = __expf(sval - mN[i]);
                pv[i] = p;
                psum[i] += p;
            }
            *(float4*)&Ps[(tx * 8 + j) * 132 + ty * 8]     = make_float4(pv[0], pv[1], pv[2], pv[3]);
            *(float4*)&Ps[(tx * 8 + j) * 132 + ty * 8 + 4] = make_float4(pv[4], pv[5], pv[6], pv[7]);
        }
#pragma unroll
        for (int i = 0; i < 8; i++) red[(ty * 8 + i) * 17 + tx] = psum[i];
        __syncthreads();

        // ---- l update (concurrent with PV) ----
        if (t < 128) {
            float ss = 0.0f;
#pragma unroll
            for (int c = 0; c < 16; c++) ss += red[t * 17 + c];
            smL[t] = smL[t] * smA[t] + ss;
        }

        // ---- O = O*alpha + P@V ----
#pragma unroll
        for (int i = 0; i < 4; i++) {
            ull ap = pack2(smA[ty * 8 + 2 * i], smA[ty * 8 + 2 * i + 1]);
#pragma unroll
            for (int j = 0; j < 4; j++) o2[i][j] = fmul2(o2[i][j], ap);
        }
#pragma unroll 8
        for (int kk = 0; kk < 128; kk++) {
            ulonglong2 ppa = *(const ulonglong2*)&Ps[kk * 132 + ty * 8];
            ulonglong2 ppb = *(const ulonglong2*)&Ps[kk * 132 + ty * 8 + 4];
            ull pp[4] = {ppa.x, ppa.y, ppb.x, ppb.y};
            ulonglong2 vda = *(const ulonglong2*)&Vsd[kk * 136 + tx * 8];
            ulonglong2 vdb = *(const ulonglong2*)&Vsd[kk * 136 + tx * 8 + 4];
            ull vd[4] = {vda.x, vda.y, vdb.x, vdb.y};
#pragma unroll
            for (int i = 0; i < 4; i++)
#pragma unroll
                for (int j = 0; j < 4; j++)
                    o2[i][j] = ffma2(pp[i], vd[j], o2[i][j]);
        }
        __syncthreads();
    }

    // ---- normalize and write merged-head output ----
#pragma unroll
    for (int rr = 0; rr < 8; rr++) {
        int i = rr >> 1;
        float linv = 1.0f / smL[ty * 8 + rr];
        float2 f0 = unpack2(o2[i][0]);
        float2 f1 = unpack2(o2[i][1]);
        float2 f2 = unpack2(o2[i][2]);
        float2 f3 = unpack2(o2[i][3]);
        float4 ov;
        if (rr & 1) { ov = make_float4(f0.y, f1.y, f2.y, f3.y); }
        else        { ov = make_float4(f0.x, f1.x, f2.x, f3.x); }
        ov.x *= linv; ov.y *= linv; ov.z *= linv; ov.w *= linv;
        *(float4*)&g_att[(b * TLEN + q0 + ty * 8 + rr) * EDIM + hofs + tx * 4] = ov;
    }
}

// ============================================================================
// LayerNorm over E=1024, one block (256 threads) per row.
// ============================================================================
__global__ __launch_bounds__(256) void ln_kernel(
    const float* __restrict__ X, const float* __restrict__ gam,
    const float* __restrict__ bet, float* __restrict__ out)
{
    const int row = blockIdx.x;
    const int t   = threadIdx.x;
    __shared__ float red[8];

    float4 x = *(const float4*)&X[row * EDIM + t * 4];
    float s = x.x + x.y + x.z + x.w;
#pragma unroll
    for (int ofs = 16; ofs; ofs >>= 1) s += __shfl_xor_sync(0xffffffffu, s, ofs);
    if ((t & 31) == 0) red[t >> 5] = s;
    __syncthreads();
    float tot = 0.0f;
#pragma unroll
    for (int i = 0; i < 8; i++) tot += red[i];
    float mu = tot * (1.0f / 1024.0f);

    float d0 = x.x - mu, d1 = x.y - mu, d2 = x.z - mu, d3 = x.w - mu;
    float sq = d0 * d0 + d1 * d1 + d2 * d2 + d3 * d3;
    __syncthreads();
#pragma unroll
    for (int ofs = 16; ofs; ofs >>= 1) sq += __shfl_xor_sync(0xffffffffu, sq, ofs);
    if ((t & 31) == 0) red[t >> 5] = sq;
    __syncthreads();
    float vtot = 0.0f;
#pragma unroll
    for (int i = 0; i < 8; i++) vtot += red[i];
    float inv = rsqrtf(vtot * (1.0f / 1024.0f) + 1e-5f);

    float4 g  = *(const float4*)&gam[t * 4];
    float4 be = *(const float4*)&bet[t * 4];
    float4 o4;
    o4.x = d0 * inv * g.x + be.x;
    o4.y = d1 * inv * g.y + be.y;
    o4.z = d2 * inv * g.z + be.z;
    o4.w = d3 * inv * g.w + be.w;
    *(float4*)&out[row * EDIM + t * 4] = o4;
}

// ============================================================================
extern "C" void kernel_launch(void* const* d_in, const int* in_sizes, int n_in,
                              void* d_out, int out_size)
{
    const float* query = (const float*)d_in[0];
    const float* key   = (const float*)d_in[1];
    const float* value = (const float*)d_in[2];
    const int*   mask  = (const int*)d_in[3];
    const float* Wq    = (const float*)d_in[4];
    const float* bq    = (const float*)d_in[5];
    const float* Wk    = (const float*)d_in[6];
    const float* bk    = (const float*)d_in[7];
    const float* Wv    = (const float*)d_in[8];
    const float* bv    = (const float*)d_in[9];
    const float* Wo    = (const float*)d_in[10];
    const float* bo    = (const float*)d_in[11];
    const float* gamma = (const float*)d_in[12];
    const float* beta  = (const float*)d_in[13];
    float* out = (float*)d_out;

    float *dq, *dk, *dv, *datt;
    cudaGetSymbolAddress((void**)&dq,   g_q);
    cudaGetSymbolAddress((void**)&dk,   g_k);
    cudaGetSymbolAddress((void**)&dv,   g_v);
    cudaGetSymbolAddress((void**)&datt, g_att);

    cudaFuncSetAttribute(attn_kernel,
                         cudaFuncAttributeMaxDynamicSharedMemorySize,
                         ATTN_SMEM_BYTES);

    dim3 gg(EDIM / 128, MROWS / 128);   // (8, 32)

    gemm_nt_bias<<<gg, 256>>>(query, Wq, bq, dq, EDIM, EDIM);
    gemm_nt_bias<<<gg, 256>>>(key,   Wk, bk, dk, EDIM, EDIM);
    gemm_nt_bias<<<gg, 256>>>(value, Wv, bv, dv, EDIM, EDIM);

    dim3 ga(TLEN / 128, BATCH * NHEAD);  // (8, 64)
    attn_kernel<<<ga, 256, ATTN_SMEM_BYTES>>>(mask);

    gemm_nt_bias<<<gg, 256>>>(datt, Wo, bo, dq, EDIM, EDIM);

    ln_kernel<<<MROWS, 256>>>(dq, gamma, beta, out);
}

// round 6
// speedup vs baseline: 1.5302x; 1.5302x over previous
#include <cuda_runtime.h>
#include <math.h>
#include <stdint.h>

#define EDIM 1024
#define TLEN 1024
#define BATCH 4
#define NHEAD 16
#define HDIM 64
#define MROWS (BATCH * TLEN)   // 4096

// ---------------- scratch (device globals: no runtime allocation) ----------
__device__ __align__(128) float g_q[(size_t)MROWS * EDIM];
__device__ __align__(128) float g_k[(size_t)MROWS * EDIM];
__device__ __align__(128) float g_v[(size_t)MROWS * EDIM];
__device__ __align__(128) float g_att[(size_t)MROWS * EDIM];
// tf32-rounded operands
__device__ __align__(128) float g_rq[(size_t)MROWS * EDIM];
__device__ __align__(128) float g_rk[(size_t)MROWS * EDIM];
__device__ __align__(128) float g_rv[(size_t)MROWS * EDIM];
__device__ __align__(128) float g_rwq[(size_t)EDIM * EDIM];
__device__ __align__(128) float g_rwk[(size_t)EDIM * EDIM];
__device__ __align__(128) float g_rwv[(size_t)EDIM * EDIM];
__device__ __align__(128) float g_rwo[(size_t)EDIM * EDIM];

// ============================ helpers =======================================
__device__ __forceinline__ uint32_t smem_u32(const void* p) {
    uint32_t a;
    asm("{ .reg .u64 t; cvta.to.shared.u64 t, %1; cvt.u32.u64 %0, t; }"
        : "=r"(a) : "l"(p));
    return a;
}
__device__ __forceinline__ void cp_async16(uint32_t dst, const void* src) {
    asm volatile("cp.async.cg.shared.global [%0], [%1], 16;"
                 :: "r"(dst), "l"(src));
}
#define CP_COMMIT() asm volatile("cp.async.commit_group;" ::: "memory")
#define CP_WAIT(n)  asm volatile("cp.async.wait_group %0;" :: "n"(n) : "memory")

__device__ __forceinline__ float rna_tf32(float x) {
    uint32_t u;
    asm("cvt.rna.tf32.f32 %0, %1;" : "=r"(u) : "f"(x));
    return __uint_as_float(u);
}

__device__ __forceinline__ void mma_tf32(float* d, const uint32_t* a,
                                         const uint32_t* b) {
    asm volatile(
        "mma.sync.aligned.m16n8k8.row.col.f32.tf32.tf32.f32 "
        "{%0,%1,%2,%3}, {%4,%5,%6,%7}, {%8,%9}, {%0,%1,%2,%3};"
        : "+f"(d[0]), "+f"(d[1]), "+f"(d[2]), "+f"(d[3])
        : "r"(a[0]), "r"(a[1]), "r"(a[2]), "r"(a[3]),
          "r"(b[0]), "r"(b[1]));
}

// ============================================================================
// round-to-nearest tf32 copy (grid-stride, float4)
// ============================================================================
__global__ __launch_bounds__(256) void round_tf32_kernel(
    const float* __restrict__ x, float* __restrict__ y, int n4)
{
    int i = blockIdx.x * blockDim.x + threadIdx.x;
    int stride = gridDim.x * blockDim.x;
    for (; i < n4; i += stride) {
        float4 v = *(const float4*)&x[i * 4];
        v.x = rna_tf32(v.x); v.y = rna_tf32(v.y);
        v.z = rna_tf32(v.z); v.w = rna_tf32(v.w);
        *(float4*)&y[i * 4] = v;
    }
}

// ============================================================================
// Tensor-core tf32 GEMM: C[M,N] = A[M,K] @ W[N,K]^T + bias  (row-major)
// 128x128 tile, BK=32, 256 threads (8 warps: 2M x 4N, 64x32 per warp),
// mma.sync.m16n8k8, cp.async double buffer. Inputs pre-rounded to tf32.
// ============================================================================
#define BK 32
#define SSTR 36                       // smem floats per row (padded, 16B-mult)
#define TILE_F (128 * SSTR)           // 4608 floats per operand tile
#define GEMM_SMEM (2 * 2 * TILE_F * 4)  // 73728 B

__global__ __launch_bounds__(256, 2) void gemm_tc(
    const float* __restrict__ A, const float* __restrict__ W,
    const float* __restrict__ bias, float* __restrict__ C)
{
    extern __shared__ float sm[];

    const int t    = threadIdx.x;
    const int wid  = t >> 5;
    const int lane = t & 31;
    const int grp  = lane >> 2;       // 0..7
    const int tig  = lane & 3;        // 0..3
    const int wm   = (wid >> 2) * 64; // warp M offset
    const int wn   = (wid & 3) * 32;  // warp N offset
    const int m0   = blockIdx.y * 128;
    const int n0   = blockIdx.x * 128;

    const int lr = t >> 1;            // loader row 0..127
    const int lc = (t & 1) * 4;       // loader chunk base (16B chunks)

    float acc[4][4][4];
#pragma unroll
    for (int mi = 0; mi < 4; mi++)
#pragma unroll
        for (int nj = 0; nj < 4; nj++)
#pragma unroll
            for (int q = 0; q < 4; q++) acc[mi][nj][q] = 0.0f;

    const uint32_t smA0 = smem_u32(sm);

    // prologue load buf 0
    {
        uint32_t dA = smA0;
        uint32_t dB = smA0 + TILE_F * 4;
#pragma unroll
        for (int j = 0; j < 4; j++) {
            int c = lc + j;
            cp_async16(dA + (lr * SSTR + c * 4) * 4,
                       A + (size_t)(m0 + lr) * EDIM + c * 4);
            cp_async16(dB + (lr * SSTR + c * 4) * 4,
                       W + (size_t)(n0 + lr) * EDIM + c * 4);
        }
    }
    CP_COMMIT();

    const int NIT = EDIM / BK;        // 32
    for (int it = 0; it < NIT; it++) {
        const int buf = it & 1;
        if (it + 1 < NIT) {
            const int nb = buf ^ 1;
            const int k0 = (it + 1) * BK;
            uint32_t dA = smA0 + nb * 2 * TILE_F * 4;
            uint32_t dB = dA + TILE_F * 4;
#pragma unroll
            for (int j = 0; j < 4; j++) {
                int c = lc + j;
                cp_async16(dA + (lr * SSTR + c * 4) * 4,
                           A + (size_t)(m0 + lr) * EDIM + k0 + c * 4);
                cp_async16(dB + (lr * SSTR + c * 4) * 4,
                           W + (size_t)(n0 + lr) * EDIM + k0 + c * 4);
            }
            CP_COMMIT();
            CP_WAIT(1);
        } else {
            CP_WAIT(0);
        }
        __syncthreads();

        const float* tA = sm + buf * 2 * TILE_F;
        const float* tB = tA + TILE_F;

#pragma unroll
        for (int ks = 0; ks < 4; ks++) {
            const int kb = ks * 8;
            uint32_t af[4][4], bf[4][2];
#pragma unroll
            for (int mi = 0; mi < 4; mi++) {
                int r = wm + mi * 16 + grp;
                af[mi][0] = __float_as_uint(tA[r * SSTR + kb + tig]);
                af[mi][1] = __float_as_uint(tA[(r + 8) * SSTR + kb + tig]);
                af[mi][2] = __float_as_uint(tA[r * SSTR + kb + tig + 4]);
                af[mi][3] = __float_as_uint(tA[(r + 8) * SSTR + kb + tig + 4]);
            }
#pragma unroll
            for (int nj = 0; nj < 4; nj++) {
                int rn = wn + nj * 8 + grp;
                bf[nj][0] = __float_as_uint(tB[rn * SSTR + kb + tig]);
                bf[nj][1] = __float_as_uint(tB[rn * SSTR + kb + tig + 4]);
            }
#pragma unroll
            for (int mi = 0; mi < 4; mi++)
#pragma unroll
                for (int nj = 0; nj < 4; nj++)
                    mma_tf32(acc[mi][nj], af[mi], bf[nj]);
        }
        __syncthreads();
    }

    // epilogue: c0,c1 at (grp, 2tig), c2,c3 at (grp+8, 2tig)
#pragma unroll
    for (int mi = 0; mi < 4; mi++) {
        int rg = m0 + wm + mi * 16 + grp;
#pragma unroll
        for (int nj = 0; nj < 4; nj++) {
            int cg = n0 + wn + nj * 8 + tig * 2;
            float2 bv = *(const float2*)&bias[cg];
            float2 o0, o1;
            o0.x = acc[mi][nj][0] + bv.x;
            o0.y = acc[mi][nj][1] + bv.y;
            o1.x = acc[mi][nj][2] + bv.x;
            o1.y = acc[mi][nj][3] + bv.y;
            *(float2*)&C[(size_t)rg * EDIM + cg]       = o0;
            *(float2*)&C[(size_t)(rg + 8) * EDIM + cg] = o1;
        }
    }
}

// ============================================================================
// Fused masked-softmax attention (proven R2 version, exact fp32).
// Output written tf32-rounded (it feeds the tf32 out-projection).
// ============================================================================
#define LROW 68
#define ATTN_SMEM_FLOATS (4 * 64 * LROW + 3 * 64)
#define ATTN_SMEM_BYTES  (ATTN_SMEM_FLOATS * 4)

__global__ __launch_bounds__(256) void attn_kernel(const int* __restrict__ mask)
{
    extern __shared__ float smf[];
    float* Qs  = smf;
    float* Ks  = Qs + 64 * LROW;   // also Ps
    float* Vs  = Ks + 64 * LROW;
    float* Ss  = Vs + 64 * LROW;
    float* smM = Ss + 64 * LROW;
    float* smL = smM + 64;
    float* smA = smL + 64;

    const int t  = threadIdx.x;
    const int tx = t & 15;
    const int ty = t >> 4;
    const int q0 = blockIdx.x * 64;
    const int bh = blockIdx.y;
    const int b  = bh >> 4;
    const int h  = bh & 15;
    const int hofs = h * HDIM;

#pragma unroll
    for (int p = 0; p < 4; p++) {
        int id   = t + p * 256;
        int rowl = id >> 4;
        int d4   = id & 15;
        float4 qv = *(const float4*)&g_q[(b * TLEN + q0 + rowl) * EDIM + hofs + d4 * 4];
        Qs[(d4 * 4 + 0) * LROW + rowl] = qv.x * 0.125f;
        Qs[(d4 * 4 + 1) * LROW + rowl] = qv.y * 0.125f;
        Qs[(d4 * 4 + 2) * LROW + rowl] = qv.z * 0.125f;
        Qs[(d4 * 4 + 3) * LROW + rowl] = qv.w * 0.125f;
    }
    if (t < 64) { smM[t] = -1e30f; smL[t] = 0.0f; }

    float o[4][4];
#pragma unroll
    for (int i = 0; i < 4; i++)
#pragma unroll
        for (int j = 0; j < 4; j++) o[i][j] = 0.0f;

    __syncthreads();

    for (int kt = 0; kt < TLEN / 64; kt++) {
#pragma unroll
        for (int p = 0; p < 4; p++) {
            int id   = t + p * 256;
            int rowl = id >> 4;
            int d4   = id & 15;
            float4 kv = *(const float4*)&g_k[(b * TLEN + kt * 64 + rowl) * EDIM + hofs + d4 * 4];
            Ks[(d4 * 4 + 0) * LROW + rowl] = kv.x;
            Ks[(d4 * 4 + 1) * LROW + rowl] = kv.y;
            Ks[(d4 * 4 + 2) * LROW + rowl] = kv.z;
            Ks[(d4 * 4 + 3) * LROW + rowl] = kv.w;
        }
        __syncthreads();

        float s[4][4];
#pragma unroll
        for (int i = 0; i < 4; i++)
#pragma unroll
            for (int j = 0; j < 4; j++) s[i][j] = 0.0f;

#pragma unroll 8
        for (int d = 0; d < 64; d++) {
            float4 qa = *(const float4*)&Qs[d * LROW + ty * 4];
            float4 kb = *(const float4*)&Ks[d * LROW + tx * 4];
            float qr[4] = {qa.x, qa.y, qa.z, qa.w};
            float kr[4] = {kb.x, kb.y, kb.z, kb.w};
#pragma unroll
            for (int i = 0; i < 4; i++)
#pragma unroll
                for (int j = 0; j < 4; j++)
                    s[i][j] = fmaf(qr[i], kr[j], s[i][j]);
        }

#pragma unroll
        for (int i = 0; i < 4; i++) {
            int qg = q0 + ty * 4 + i;
            int4 mv = *(const int4*)&mask[(b * TLEN + qg) * TLEN + kt * 64 + tx * 4];
            float4 sv;
            sv.x = (mv.x == 0) ? -1.0e9f : s[i][0];
            sv.y = (mv.y == 0) ? -1.0e9f : s[i][1];
            sv.z = (mv.z == 0) ? -1.0e9f : s[i][2];
            sv.w = (mv.w == 0) ? -1.0e9f : s[i][3];
            *(float4*)&Ss[(ty * 4 + i) * LROW + tx * 4] = sv;
        }
        __syncthreads();

        if (t < 64) {
            const int r = t;
            float mOld = smM[r];
            float mNew = mOld;
#pragma unroll 8
            for (int j = 0; j < 64; j++)
                mNew = fmaxf(mNew, Ss[r * LROW + j]);
            float alpha = __expf(mOld - mNew);
            float l = smL[r] * alpha;
#pragma unroll 8
            for (int j = 0; j < 64; j++) {
                float p = __expf(Ss[r * LROW + j] - mNew);
                l += p;
                Ks[j * LROW + r] = p;   // Ps[k][q]
            }
            smM[r] = mNew; smL[r] = l; smA[r] = alpha;
        } else {
            for (int id = t - 64; id < 1024; id += 192) {
                int rowl = id >> 4;
                int d4   = id & 15;
                float4 vv = *(const float4*)&g_v[(b * TLEN + kt * 64 + rowl) * EDIM + hofs + d4 * 4];
                *(float4*)&Vs[rowl * LROW + d4 * 4] = vv;
            }
        }
        __syncthreads();

#pragma unroll
        for (int i = 0; i < 4; i++) {
            float a = smA[ty * 4 + i];
#pragma unroll
            for (int j = 0; j < 4; j++) o[i][j] *= a;
        }
#pragma unroll 8
        for (int kk = 0; kk < 64; kk++) {
            float4 pa = *(const float4*)&Ks[kk * LROW + ty * 4];
            float4 vb = *(const float4*)&Vs[kk * LROW + tx * 4];
            float pr[4] = {pa.x, pa.y, pa.z, pa.w};
            float vr[4] = {vb.x, vb.y, vb.z, vb.w};
#pragma unroll
            for (int i = 0; i < 4; i++)
#pragma unroll
                for (int j = 0; j < 4; j++)
                    o[i][j] = fmaf(pr[i], vr[j], o[i][j]);
        }
        __syncthreads();
    }

#pragma unroll
    for (int i = 0; i < 4; i++) {
        float linv = 1.0f / smL[ty * 4 + i];
        float4 ov;
        ov.x = rna_tf32(o[i][0] * linv);
        ov.y = rna_tf32(o[i][1] * linv);
        ov.z = rna_tf32(o[i][2] * linv);
        ov.w = rna_tf32(o[i][3] * linv);
        *(float4*)&g_att[(b * TLEN + q0 + ty * 4 + i) * EDIM + hofs + tx * 4] = ov;
    }
}

// ============================================================================
// LayerNorm over E=1024, one block (256 threads) per row.
// ============================================================================
__global__ __launch_bounds__(256) void ln_kernel(
    const float* __restrict__ X, const float* __restrict__ gam,
    const float* __restrict__ bet, float* __restrict__ out)
{
    const int row = blockIdx.x;
    const int t   = threadIdx.x;
    __shared__ float red[8];

    float4 x = *(const float4*)&X[row * EDIM + t * 4];
    float s = x.x + x.y + x.z + x.w;
#pragma unroll
    for (int ofs = 16; ofs; ofs >>= 1) s += __shfl_xor_sync(0xffffffffu, s, ofs);
    if ((t & 31) == 0) red[t >> 5] = s;
    __syncthreads();
    float tot = 0.0f;
#pragma unroll
    for (int i = 0; i < 8; i++) tot += red[i];
    float mu = tot * (1.0f / 1024.0f);

    float d0 = x.x - mu, d1 = x.y - mu, d2 = x.z - mu, d3 = x.w - mu;
    float sq = d0 * d0 + d1 * d1 + d2 * d2 + d3 * d3;
    __syncthreads();
#pragma unroll
    for (int ofs = 16; ofs; ofs >>= 1) sq += __shfl_xor_sync(0xffffffffu, sq, ofs);
    if ((t & 31) == 0) red[t >> 5] = sq;
    __syncthreads();
    float vtot = 0.0f;
#pragma unroll
    for (int i = 0; i < 8; i++) vtot += red[i];
    float inv = rsqrtf(vtot * (1.0f / 1024.0f) + 1e-5f);

    float4 g  = *(const float4*)&gam[t * 4];
    float4 be = *(const float4*)&bet[t * 4];
    float4 o4;
    o4.x = d0 * inv * g.x + be.x;
    o4.y = d1 * inv * g.y + be.y;
    o4.z = d2 * inv * g.z + be.z;
    o4.w = d3 * inv * g.w + be.w;
    *(float4*)&out[row * EDIM + t * 4] = o4;
}

// ============================================================================
extern "C" void kernel_launch(void* const* d_in, const int* in_sizes, int n_in,
                              void* d_out, int out_size)
{
    const float* query = (const float*)d_in[0];
    const float* key   = (const float*)d_in[1];
    const float* value = (const float*)d_in[2];
    const int*   mask  = (const int*)d_in[3];
    const float* Wq    = (const float*)d_in[4];
    const float* bq    = (const float*)d_in[5];
    const float* Wk    = (const float*)d_in[6];
    const float* bk    = (const float*)d_in[7];
    const float* Wv    = (const float*)d_in[8];
    const float* bv    = (const float*)d_in[9];
    const float* Wo    = (const float*)d_in[10];
    const float* bo    = (const float*)d_in[11];
    const float* gamma = (const float*)d_in[12];
    const float* beta  = (const float*)d_in[13];
    float* out = (float*)d_out;

    float *dq, *dk, *dv, *datt;
    float *rq, *rk, *rv, *rwq, *rwk, *rwv, *rwo;
    cudaGetSymbolAddress((void**)&dq,   g_q);
    cudaGetSymbolAddress((void**)&dk,   g_k);
    cudaGetSymbolAddress((void**)&dv,   g_v);
    cudaGetSymbolAddress((void**)&datt, g_att);
    cudaGetSymbolAddress((void**)&rq,   g_rq);
    cudaGetSymbolAddress((void**)&rk,   g_rk);
    cudaGetSymbolAddress((void**)&rv,   g_rv);
    cudaGetSymbolAddress((void**)&rwq,  g_rwq);
    cudaGetSymbolAddress((void**)&rwk,  g_rwk);
    cudaGetSymbolAddress((void**)&rwv,  g_rwv);
    cudaGetSymbolAddress((void**)&rwo,  g_rwo);

    cudaFuncSetAttribute(gemm_tc,
                         cudaFuncAttributeMaxDynamicSharedMemorySize, GEMM_SMEM);
    cudaFuncSetAttribute(attn_kernel,
                         cudaFuncAttributeMaxDynamicSharedMemorySize, ATTN_SMEM_BYTES);

    const int ACT4 = (MROWS * EDIM) / 4;   // 1048576
    const int WT4  = (EDIM * EDIM) / 4;    // 262144

    // tf32 pre-rounding (rna) of all GEMM operands
    round_tf32_kernel<<<2048, 256>>>(query, rq, ACT4);
    round_tf32_kernel<<<2048, 256>>>(key,   rk, ACT4);
    round_tf32_kernel<<<2048, 256>>>(value, rv, ACT4);
    round_tf32_kernel<<<1024, 256>>>(Wq, rwq, WT4);
    round_tf32_kernel<<<1024, 256>>>(Wk, rwk, WT4);
    round_tf32_kernel<<<1024, 256>>>(Wv, rwv, WT4);
    round_tf32_kernel<<<1024, 256>>>(Wo, rwo, WT4);

    dim3 gg(EDIM / 128, MROWS / 128);   // (8, 32)

    gemm_tc<<<gg, 256, GEMM_SMEM>>>(rq, rwq, bq, dq);
    gemm_tc<<<gg, 256, GEMM_SMEM>>>(rk, rwk, bk, dk);
    gemm_tc<<<gg, 256, GEMM_SMEM>>>(rv, rwv, bv, dv);

    dim3 ga(TLEN / 64, BATCH * NHEAD);  // (16, 64)
    attn_kernel<<<ga, 256, ATTN_SMEM_BYTES>>>(mask);

    gemm_tc<<<gg, 256, GEMM_SMEM>>>(datt, rwo, bo, dq);

    ln_kernel<<<MROWS, 256>>>(dq, gamma, beta, out);
}

// round 7
// speedup vs baseline: 2.3329x; 1.5246x over previous
#include <cuda_runtime.h>
#include <math.h>
#include <stdint.h>

#define EDIM 1024
#define TLEN 1024
#define BATCH 4
#define NHEAD 16
#define HDIM 64
#define MROWS (BATCH * TLEN)   // 4096

// ---------------- scratch (device globals: no runtime allocation) ----------
__device__ __align__(128) float g_q[(size_t)MROWS * EDIM];
__device__ __align__(128) float g_k[(size_t)MROWS * EDIM];
__device__ __align__(128) float g_v[(size_t)MROWS * EDIM];
__device__ __align__(128) float g_att[(size_t)MROWS * EDIM];
// tf32-rounded operands
__device__ __align__(128) float g_rq[(size_t)MROWS * EDIM];
__device__ __align__(128) float g_rk[(size_t)MROWS * EDIM];
__device__ __align__(128) float g_rv[(size_t)MROWS * EDIM];
__device__ __align__(128) float g_rwq[(size_t)EDIM * EDIM];
__device__ __align__(128) float g_rwk[(size_t)EDIM * EDIM];
__device__ __align__(128) float g_rwv[(size_t)EDIM * EDIM];
__device__ __align__(128) float g_rwo[(size_t)EDIM * EDIM];

// ============================ helpers =======================================
__device__ __forceinline__ uint32_t smem_u32(const void* p) {
    uint32_t a;
    asm("{ .reg .u64 t; cvta.to.shared.u64 t, %1; cvt.u32.u64 %0, t; }"
        : "=r"(a) : "l"(p));
    return a;
}
__device__ __forceinline__ void cp_async16(uint32_t dst, const void* src) {
    asm volatile("cp.async.cg.shared.global [%0], [%1], 16;"
                 :: "r"(dst), "l"(src));
}
#define CP_COMMIT() asm volatile("cp.async.commit_group;" ::: "memory")
#define CP_WAIT(n)  asm volatile("cp.async.wait_group %0;" :: "n"(n) : "memory")

__device__ __forceinline__ float rna_tf32(float x) {
    uint32_t u;
    asm("cvt.rna.tf32.f32 %0, %1;" : "=r"(u) : "f"(x));
    return __uint_as_float(u);
}

__device__ __forceinline__ void mma_tf32(float* d, const uint32_t* a,
                                         const uint32_t* b) {
    asm volatile(
        "mma.sync.aligned.m16n8k8.row.col.f32.tf32.tf32.f32 "
        "{%0,%1,%2,%3}, {%4,%5,%6,%7}, {%8,%9}, {%0,%1,%2,%3};"
        : "+f"(d[0]), "+f"(d[1]), "+f"(d[2]), "+f"(d[3])
        : "r"(a[0]), "r"(a[1]), "r"(a[2]), "r"(a[3]),
          "r"(b[0]), "r"(b[1]));
}

// ============================================================================
// round-to-nearest tf32 copy (grid-stride, float4)
// ============================================================================
__global__ __launch_bounds__(256) void round_tf32_kernel(
    const float* __restrict__ x, float* __restrict__ y, int n4)
{
    int i = blockIdx.x * blockDim.x + threadIdx.x;
    int stride = gridDim.x * blockDim.x;
    for (; i < n4; i += stride) {
        float4 v = *(const float4*)&x[i * 4];
        v.x = rna_tf32(v.x); v.y = rna_tf32(v.y);
        v.z = rna_tf32(v.z); v.w = rna_tf32(v.w);
        *(float4*)&y[i * 4] = v;
    }
}

// ============================================================================
// Tensor-core tf32 GEMM: C[M,N] = A[M,K] @ W[N,K]^T + bias  (row-major)
// 128x128 tile, BK=32, 256 threads (8 warps: 2M x 4N, 64x32 per warp),
// mma.sync.m16n8k8, cp.async double buffer. Inputs pre-rounded to tf32.
// ============================================================================
#define BK 32
#define SSTR 36
#define TILE_F (128 * SSTR)
#define GEMM_SMEM (2 * 2 * TILE_F * 4)

__global__ __launch_bounds__(256, 2) void gemm_tc(
    const float* __restrict__ A, const float* __restrict__ W,
    const float* __restrict__ bias, float* __restrict__ C)
{
    extern __shared__ float sm[];

    const int t    = threadIdx.x;
    const int wid  = t >> 5;
    const int lane = t & 31;
    const int grp  = lane >> 2;
    const int tig  = lane & 3;
    const int wm   = (wid >> 2) * 64;
    const int wn   = (wid & 3) * 32;
    const int m0   = blockIdx.y * 128;
    const int n0   = blockIdx.x * 128;

    const int lr = t >> 1;
    const int lc = (t & 1) * 4;

    float acc[4][4][4];
#pragma unroll
    for (int mi = 0; mi < 4; mi++)
#pragma unroll
        for (int nj = 0; nj < 4; nj++)
#pragma unroll
            for (int q = 0; q < 4; q++) acc[mi][nj][q] = 0.0f;

    const uint32_t smA0 = smem_u32(sm);

    {
        uint32_t dA = smA0;
        uint32_t dB = smA0 + TILE_F * 4;
#pragma unroll
        for (int j = 0; j < 4; j++) {
            int c = lc + j;
            cp_async16(dA + (lr * SSTR + c * 4) * 4,
                       A + (size_t)(m0 + lr) * EDIM + c * 4);
            cp_async16(dB + (lr * SSTR + c * 4) * 4,
                       W + (size_t)(n0 + lr) * EDIM + c * 4);
        }
    }
    CP_COMMIT();

    const int NIT = EDIM / BK;
    for (int it = 0; it < NIT; it++) {
        const int buf = it & 1;
        if (it + 1 < NIT) {
            const int nb = buf ^ 1;
            const int k0 = (it + 1) * BK;
            uint32_t dA = smA0 + nb * 2 * TILE_F * 4;
            uint32_t dB = dA + TILE_F * 4;
#pragma unroll
            for (int j = 0; j < 4; j++) {
                int c = lc + j;
                cp_async16(dA + (lr * SSTR + c * 4) * 4,
                           A + (size_t)(m0 + lr) * EDIM + k0 + c * 4);
                cp_async16(dB + (lr * SSTR + c * 4) * 4,
                           W + (size_t)(n0 + lr) * EDIM + k0 + c * 4);
            }
            CP_COMMIT();
            CP_WAIT(1);
        } else {
            CP_WAIT(0);
        }
        __syncthreads();

        const float* tA = sm + buf * 2 * TILE_F;
        const float* tB = tA + TILE_F;

#pragma unroll
        for (int ks = 0; ks < 4; ks++) {
            const int kb = ks * 8;
            uint32_t af[4][4], bf[4][2];
#pragma unroll
            for (int mi = 0; mi < 4; mi++) {
                int r = wm + mi * 16 + grp;
                af[mi][0] = __float_as_uint(tA[r * SSTR + kb + tig]);
                af[mi][1] = __float_as_uint(tA[(r + 8) * SSTR + kb + tig]);
                af[mi][2] = __float_as_uint(tA[r * SSTR + kb + tig + 4]);
                af[mi][3] = __float_as_uint(tA[(r + 8) * SSTR + kb + tig + 4]);
            }
#pragma unroll
            for (int nj = 0; nj < 4; nj++) {
                int rn = wn + nj * 8 + grp;
                bf[nj][0] = __float_as_uint(tB[rn * SSTR + kb + tig]);
                bf[nj][1] = __float_as_uint(tB[rn * SSTR + kb + tig + 4]);
            }
#pragma unroll
            for (int mi = 0; mi < 4; mi++)
#pragma unroll
                for (int nj = 0; nj < 4; nj++)
                    mma_tf32(acc[mi][nj], af[mi], bf[nj]);
        }
        __syncthreads();
    }

#pragma unroll
    for (int mi = 0; mi < 4; mi++) {
        int rg = m0 + wm + mi * 16 + grp;
#pragma unroll
        for (int nj = 0; nj < 4; nj++) {
            int cg = n0 + wn + nj * 8 + tig * 2;
            float2 bv = *(const float2*)&bias[cg];
            float2 o0, o1;
            o0.x = acc[mi][nj][0] + bv.x;
            o0.y = acc[mi][nj][1] + bv.y;
            o1.x = acc[mi][nj][2] + bv.x;
            o1.y = acc[mi][nj][3] + bv.y;
            *(float2*)&C[(size_t)rg * EDIM + cg]       = o0;
            *(float2*)&C[(size_t)(rg + 8) * EDIM + cg] = o1;
        }
    }
}

// ============================================================================
// Tensor-core flash attention: 64 q-rows x (b*h) per block, 256 threads,
// 8 warps as 4M x 2N. S and PV on mma.sync tf32; softmax stats exact fp32.
// smem: Qs[64][68] [q][d] (tf32, x0.125), Ks[64][68] [k][d] (tf32),
//       Vt[64][68] [d][k] rotated by (k+d)&63 (tf32), Ps[64][68] [q][k] (tf32),
//       red[64][2], smM/smL/smA[64].
// ============================================================================
#define APAD 68
#define ATTN_TC_FLOATS (4 * 64 * APAD + 128 + 192)
#define ATTN_TC_BYTES  (ATTN_TC_FLOATS * 4)

__global__ __launch_bounds__(256) void attn_tc(const int* __restrict__ mask)
{
    extern __shared__ float smf[];
    float* Qs  = smf;
    float* Ks  = smf + 64 * APAD;
    float* Vt  = smf + 2 * 64 * APAD;
    float* Ps  = smf + 3 * 64 * APAD;
    float* red = smf + 4 * 64 * APAD;   // [64][2]
    float* smM = red + 128;
    float* smL = smM + 64;
    float* smA = smL + 64;

    const int t    = threadIdx.x;
    const int wid  = t >> 5;
    const int lane = t & 31;
    const int grp  = lane >> 2;
    const int tig  = lane & 3;
    const int wm   = (wid & 3) * 16;
    const int wn   = (wid >> 2) * 32;
    const int wnx  = wid >> 2;          // 0 or 1
    const int q0   = blockIdx.x * 64;
    const int bh   = blockIdx.y;
    const int b    = bh >> 4;
    const int h    = bh & 15;
    const int hofs = h * HDIM;

    // ---- load Q tile [q][d], tf32-rounded, pre-scaled 1/8 ----
#pragma unroll
    for (int p = 0; p < 4; p++) {
        int id  = t + p * 256;
        int row = id >> 4;
        int c4  = id & 15;
        float4 qv = *(const float4*)&g_q[(size_t)(b * TLEN + q0 + row) * EDIM + hofs + c4 * 4];
        qv.x = rna_tf32(qv.x * 0.125f); qv.y = rna_tf32(qv.y * 0.125f);
        qv.z = rna_tf32(qv.z * 0.125f); qv.w = rna_tf32(qv.w * 0.125f);
        *(float4*)&Qs[row * APAD + c4 * 4] = qv;
    }
    if (t < 64) { smM[t] = -1e30f; smL[t] = 0.0f; }

    float o[4][4];
#pragma unroll
    for (int nf = 0; nf < 4; nf++)
#pragma unroll
        for (int q = 0; q < 4; q++) o[nf][q] = 0.0f;

    __syncthreads();

    const int r0 = wm + grp;        // first owned row
    const int r1 = wm + grp + 8;    // second owned row

    for (int kt = 0; kt < TLEN / 64; kt++) {
        // ---- load K [k][d] and V -> Vt [d][k] (rotated), tf32-rounded ----
#pragma unroll
        for (int p = 0; p < 4; p++) {
            int id  = t + p * 256;
            int row = id >> 4;
            int c4  = id & 15;
            const size_t gofs = (size_t)(b * TLEN + kt * 64 + row) * EDIM + hofs + c4 * 4;
            float4 kv = *(const float4*)&g_k[gofs];
            kv.x = rna_tf32(kv.x); kv.y = rna_tf32(kv.y);
            kv.z = rna_tf32(kv.z); kv.w = rna_tf32(kv.w);
            *(float4*)&Ks[row * APAD + c4 * 4] = kv;
            float4 vv = *(const float4*)&g_v[gofs];
            int d0 = c4 * 4;
            Vt[(d0 + 0) * APAD + ((row + d0 + 0) & 63)] = rna_tf32(vv.x);
            Vt[(d0 + 1) * APAD + ((row + d0 + 1) & 63)] = rna_tf32(vv.y);
            Vt[(d0 + 2) * APAD + ((row + d0 + 2) & 63)] = rna_tf32(vv.z);
            Vt[(d0 + 3) * APAD + ((row + d0 + 3) & 63)] = rna_tf32(vv.w);
        }
        __syncthreads();

        // ---- S = Q @ K^T via mma ----
        float s[4][4];
#pragma unroll
        for (int nf = 0; nf < 4; nf++)
#pragma unroll
            for (int q = 0; q < 4; q++) s[nf][q] = 0.0f;

#pragma unroll
        for (int ks = 0; ks < 8; ks++) {
            const int kb = ks * 8;
            uint32_t af[4];
            af[0] = __float_as_uint(Qs[r0 * APAD + kb + tig]);
            af[1] = __float_as_uint(Qs[r1 * APAD + kb + tig]);
            af[2] = __float_as_uint(Qs[r0 * APAD + kb + tig + 4]);
            af[3] = __float_as_uint(Qs[r1 * APAD + kb + tig + 4]);
#pragma unroll
            for (int nf = 0; nf < 4; nf++) {
                int rn = wn + nf * 8 + grp;
                uint32_t bf[2];
                bf[0] = __float_as_uint(Ks[rn * APAD + kb + tig]);
                bf[1] = __float_as_uint(Ks[rn * APAD + kb + tig + 4]);
                mma_tf32(s[nf], af, bf);
            }
        }

        // ---- mask + per-thread max ----
        float mx0 = -1e30f, mx1 = -1e30f;
        const size_t mbase = (size_t)(b * TLEN + q0 + r0) * TLEN + kt * 64 + wn + tig * 2;
#pragma unroll
        for (int nf = 0; nf < 4; nf++) {
            int2 m0 = *(const int2*)&mask[mbase + nf * 8];
            int2 m1 = *(const int2*)&mask[mbase + (size_t)8 * TLEN + nf * 8];
            s[nf][0] = (m0.x == 0) ? -1.0e9f : s[nf][0];
            s[nf][1] = (m0.y == 0) ? -1.0e9f : s[nf][1];
            s[nf][2] = (m1.x == 0) ? -1.0e9f : s[nf][2];
            s[nf][3] = (m1.y == 0) ? -1.0e9f : s[nf][3];
            mx0 = fmaxf(mx0, fmaxf(s[nf][0], s[nf][1]));
            mx1 = fmaxf(mx1, fmaxf(s[nf][2], s[nf][3]));
        }
        mx0 = fmaxf(mx0, __shfl_xor_sync(0xffffffffu, mx0, 1));
        mx0 = fmaxf(mx0, __shfl_xor_sync(0xffffffffu, mx0, 2));
        mx1 = fmaxf(mx1, __shfl_xor_sync(0xffffffffu, mx1, 1));
        mx1 = fmaxf(mx1, __shfl_xor_sync(0xffffffffu, mx1, 2));
        if (tig == 0) {
            red[r0 * 2 + wnx] = mx0;
            red[r1 * 2 + wnx] = mx1;
        }
        __syncthreads();

        // ---- online stats update ----
        if (t < 64) {
            float rm   = fmaxf(red[t * 2], red[t * 2 + 1]);
            float mOld = smM[t];
            float mNew = fmaxf(mOld, rm);
            smA[t] = __expf(mOld - mNew);
            smM[t] = mNew;
        }
        __syncthreads();

        // ---- P = exp(S - m), store tf32 Ps[q][k], partial sums ----
        const float m0v = smM[r0], m1v = smM[r1];
        float sum0 = 0.0f, sum1 = 0.0f;
#pragma unroll
        for (int nf = 0; nf < 4; nf++) {
            float p00 = __expf(s[nf][0] - m0v);
            float p01 = __expf(s[nf][1] - m0v);
            float p10 = __expf(s[nf][2] - m1v);
            float p11 = __expf(s[nf][3] - m1v);
            sum0 += p00 + p01;
            sum1 += p10 + p11;
            int col = wn + nf * 8 + tig * 2;
            *(float2*)&Ps[r0 * APAD + col] = make_float2(rna_tf32(p00), rna_tf32(p01));
            *(float2*)&Ps[r1 * APAD + col] = make_float2(rna_tf32(p10), rna_tf32(p11));
        }

        // ---- rescale O by alpha ----
        const float a0 = smA[r0], a1 = smA[r1];
#pragma unroll
        for (int nf = 0; nf < 4; nf++) {
            o[nf][0] *= a0; o[nf][1] *= a0;
            o[nf][2] *= a1; o[nf][3] *= a1;
        }

        sum0 += __shfl_xor_sync(0xffffffffu, sum0, 1);
        sum0 += __shfl_xor_sync(0xffffffffu, sum0, 2);
        sum1 += __shfl_xor_sync(0xffffffffu, sum1, 1);
        sum1 += __shfl_xor_sync(0xffffffffu, sum1, 2);
        if (tig == 0) {
            red[r0 * 2 + wnx] = sum0;
            red[r1 * 2 + wnx] = sum1;
        }
        __syncthreads();

        if (t < 64)
            smL[t] = smL[t] * smA[t] + red[t * 2] + red[t * 2 + 1];

        // ---- O += P @ V via mma (V as [d][k], rotated index) ----
#pragma unroll
        for (int ks = 0; ks < 8; ks++) {
            const int kb = ks * 8;
            uint32_t af[4];
            af[0] = __float_as_uint(Ps[r0 * APAD + kb + tig]);
            af[1] = __float_as_uint(Ps[r1 * APAD + kb + tig]);
            af[2] = __float_as_uint(Ps[r0 * APAD + kb + tig + 4]);
            af[3] = __float_as_uint(Ps[r1 * APAD + kb + tig + 4]);
#pragma unroll
            for (int nf = 0; nf < 4; nf++) {
                int n = wn + nf * 8 + grp;   // d index
                uint32_t bf[2];
                bf[0] = __float_as_uint(Vt[n * APAD + ((kb + tig + n) & 63)]);
                bf[1] = __float_as_uint(Vt[n * APAD + ((kb + tig + 4 + n) & 63)]);
                mma_tf32(o[nf], af, bf);
            }
        }
        __syncthreads();
    }

    // ---- normalize and write (tf32-rounded: feeds tf32 out-projection) ----
    const float linv0 = 1.0f / smL[r0];
    const float linv1 = 1.0f / smL[r1];
    const size_t orow0 = (size_t)(b * TLEN + q0 + r0) * EDIM + hofs;
    const size_t orow1 = (size_t)(b * TLEN + q0 + r1) * EDIM + hofs;
#pragma unroll
    for (int nf = 0; nf < 4; nf++) {
        int col = wn + nf * 8 + tig * 2;
        *(float2*)&g_att[orow0 + col] =
            make_float2(rna_tf32(o[nf][0] * linv0), rna_tf32(o[nf][1] * linv0));
        *(float2*)&g_att[orow1 + col] =
            make_float2(rna_tf32(o[nf][2] * linv1), rna_tf32(o[nf][3] * linv1));
    }
}

// ============================================================================
// LayerNorm over E=1024, one block (256 threads) per row.
// ============================================================================
__global__ __launch_bounds__(256) void ln_kernel(
    const float* __restrict__ X, const float* __restrict__ gam,
    const float* __restrict__ bet, float* __restrict__ out)
{
    const int row = blockIdx.x;
    const int t   = threadIdx.x;
    __shared__ float red[8];

    float4 x = *(const float4*)&X[row * EDIM + t * 4];
    float s = x.x + x.y + x.z + x.w;
#pragma unroll
    for (int ofs = 16; ofs; ofs >>= 1) s += __shfl_xor_sync(0xffffffffu, s, ofs);
    if ((t & 31) == 0) red[t >> 5] = s;
    __syncthreads();
    float tot = 0.0f;
#pragma unroll
    for (int i = 0; i < 8; i++) tot += red[i];
    float mu = tot * (1.0f / 1024.0f);

    float d0 = x.x - mu, d1 = x.y - mu, d2 = x.z - mu, d3 = x.w - mu;
    float sq = d0 * d0 + d1 * d1 + d2 * d2 + d3 * d3;
    __syncthreads();
#pragma unroll
    for (int ofs = 16; ofs; ofs >>= 1) sq += __shfl_xor_sync(0xffffffffu, sq, ofs);
    if ((t & 31) == 0) red[t >> 5] = sq;
    __syncthreads();
    float vtot = 0.0f;
#pragma unroll
    for (int i = 0; i < 8; i++) vtot += red[i];
    float inv = rsqrtf(vtot * (1.0f / 1024.0f) + 1e-5f);

    float4 g  = *(const float4*)&gam[t * 4];
    float4 be = *(const float4*)&bet[t * 4];
    float4 o4;
    o4.x = d0 * inv * g.x + be.x;
    o4.y = d1 * inv * g.y + be.y;
    o4.z = d2 * inv * g.z + be.z;
    o4.w = d3 * inv * g.w + be.w;
    *(float4*)&out[row * EDIM + t * 4] = o4;
}

// ============================================================================
extern "C" void kernel_launch(void* const* d_in, const int* in_sizes, int n_in,
                              void* d_out, int out_size)
{
    const float* query = (const float*)d_in[0];
    const float* key   = (const float*)d_in[1];
    const float* value = (const float*)d_in[2];
    const int*   mask  = (const int*)d_in[3];
    const float* Wq    = (const float*)d_in[4];
    const float* bq    = (const float*)d_in[5];
    const float* Wk    = (const float*)d_in[6];
    const float* bk    = (const float*)d_in[7];
    const float* Wv    = (const float*)d_in[8];
    const float* bv    = (const float*)d_in[9];
    const float* Wo    = (const float*)d_in[10];
    const float* bo    = (const float*)d_in[11];
    const float* gamma = (const float*)d_in[12];
    const float* beta  = (const float*)d_in[13];
    float* out = (float*)d_out;

    float *dq, *dk, *dv, *datt;
    float *rq, *rk, *rv, *rwq, *rwk, *rwv, *rwo;
    cudaGetSymbolAddress((void**)&dq,   g_q);
    cudaGetSymbolAddress((void**)&dk,   g_k);
    cudaGetSymbolAddress((void**)&dv,   g_v);
    cudaGetSymbolAddress((void**)&datt, g_att);
    cudaGetSymbolAddress((void**)&rq,   g_rq);
    cudaGetSymbolAddress((void**)&rk,   g_rk);
    cudaGetSymbolAddress((void**)&rv,   g_rv);
    cudaGetSymbolAddress((void**)&rwq,  g_rwq);
    cudaGetSymbolAddress((void**)&rwk,  g_rwk);
    cudaGetSymbolAddress((void**)&rwv,  g_rwv);
    cudaGetSymbolAddress((void**)&rwo,  g_rwo);

    cudaFuncSetAttribute(gemm_tc,
                         cudaFuncAttributeMaxDynamicSharedMemorySize, GEMM_SMEM);
    cudaFuncSetAttribute(attn_tc,
                         cudaFuncAttributeMaxDynamicSharedMemorySize, ATTN_TC_BYTES);

    const int ACT4 = (MROWS * EDIM) / 4;
    const int WT4  = (EDIM * EDIM) / 4;

    round_tf32_kernel<<<2048, 256>>>(query, rq, ACT4);
    round_tf32_kernel<<<2048, 256>>>(key,   rk, ACT4);
    round_tf32_kernel<<<2048, 256>>>(value, rv, ACT4);
    round_tf32_kernel<<<1024, 256>>>(Wq, rwq, WT4);
    round_tf32_kernel<<<1024, 256>>>(Wk, rwk, WT4);
    round_tf32_kernel<<<1024, 256>>>(Wv, rwv, WT4);
    round_tf32_kernel<<<1024, 256>>>(Wo, rwo, WT4);

    dim3 gg(EDIM / 128, MROWS / 128);   // (8, 32)

    gemm_tc<<<gg, 256, GEMM_SMEM>>>(rq, rwq, bq, dq);
    gemm_tc<<<gg, 256, GEMM_SMEM>>>(rk, rwk, bk, dk);
    gemm_tc<<<gg, 256, GEMM_SMEM>>>(rv, rwv, bv, dv);

    dim3 ga(TLEN / 64, BATCH * NHEAD);  // (16, 64)
    attn_tc<<<ga, 256, ATTN_TC_BYTES>>>(mask);

    gemm_tc<<<gg, 256, GEMM_SMEM>>>(datt, rwo, bo, dq);

    ln_kernel<<<MROWS, 256>>>(dq, gamma, beta, out);
}

// round 8
// speedup vs baseline: 2.5339x; 1.0862x over previous
#include <cuda_runtime.h>
#include <math.h>
#include <stdint.h>

#define EDIM 1024
#define TLEN 1024
#define BATCH 4
#define NHEAD 16
#define HDIM 64
#define MROWS (BATCH * TLEN)   // 4096

// ---------------- scratch (device globals: no runtime allocation) ----------
__device__ __align__(128) float g_q[(size_t)MROWS * EDIM];   // rounded, x0.125
__device__ __align__(128) float g_k[(size_t)MROWS * EDIM];   // rounded
__device__ __align__(128) float g_v[(size_t)MROWS * EDIM];   // rounded
__device__ __align__(128) float g_att[(size_t)MROWS * EDIM]; // rounded
__device__ __align__(128) float g_rq[(size_t)MROWS * EDIM];
__device__ __align__(128) float g_rk[(size_t)MROWS * EDIM];
__device__ __align__(128) float g_rv[(size_t)MROWS * EDIM];
__device__ __align__(128) float g_rwq[(size_t)EDIM * EDIM];
__device__ __align__(128) float g_rwk[(size_t)EDIM * EDIM];
__device__ __align__(128) float g_rwv[(size_t)EDIM * EDIM];
__device__ __align__(128) float g_rwo[(size_t)EDIM * EDIM];

// ============================ helpers =======================================
__device__ __forceinline__ uint32_t smem_u32(const void* p) {
    uint32_t a;
    asm("{ .reg .u64 t; cvta.to.shared.u64 t, %1; cvt.u32.u64 %0, t; }"
        : "=r"(a) : "l"(p));
    return a;
}
__device__ __forceinline__ void cp_async16(uint32_t dst, const void* src) {
    asm volatile("cp.async.cg.shared.global [%0], [%1], 16;"
                 :: "r"(dst), "l"(src));
}
#define CP_COMMIT() asm volatile("cp.async.commit_group;" ::: "memory")
#define CP_WAIT(n)  asm volatile("cp.async.wait_group %0;" :: "n"(n) : "memory")

__device__ __forceinline__ float rna_tf32(float x) {
    uint32_t u;
    asm("cvt.rna.tf32.f32 %0, %1;" : "=r"(u) : "f"(x));
    return __uint_as_float(u);
}

__device__ __forceinline__ void mma_tf32(float* d, const uint32_t* a,
                                         const uint32_t* b) {
    asm volatile(
        "mma.sync.aligned.m16n8k8.row.col.f32.tf32.tf32.f32 "
        "{%0,%1,%2,%3}, {%4,%5,%6,%7}, {%8,%9}, {%0,%1,%2,%3};"
        : "+f"(d[0]), "+f"(d[1]), "+f"(d[2]), "+f"(d[3])
        : "r"(a[0]), "r"(a[1]), "r"(a[2]), "r"(a[3]),
          "r"(b[0]), "r"(b[1]));
}

// ============================================================================
// round-to-nearest tf32 copy (grid-stride, float4)
// ============================================================================
__global__ __launch_bounds__(256) void round_tf32_kernel(
    const float* __restrict__ x, float* __restrict__ y, int n4)
{
    int i = blockIdx.x * blockDim.x + threadIdx.x;
    int stride = gridDim.x * blockDim.x;
    for (; i < n4; i += stride) {
        float4 v = *(const float4*)&x[i * 4];
        v.x = rna_tf32(v.x); v.y = rna_tf32(v.y);
        v.z = rna_tf32(v.z); v.w = rna_tf32(v.w);
        *(float4*)&y[i * 4] = v;
    }
}

// ============================================================================
// Tensor-core tf32 GEMM: C = (A @ W^T + bias) * oscale [, rna-rounded]
// 128x128 tile, BK=32, 256 threads (8 warps: 2M x 4N), mma.m16n8k8,
// cp.async double buffer, ONE sync per k-iter.
// ============================================================================
#define BK 32
#define SSTR 36
#define TILE_F (128 * SSTR)
#define GEMM_SMEM (2 * 2 * TILE_F * 4)

__global__ __launch_bounds__(256, 2) void gemm_tc(
    const float* __restrict__ A, const float* __restrict__ W,
    const float* __restrict__ bias, float* __restrict__ C,
    float oscale, int oround)
{
    extern __shared__ float sm[];

    const int t    = threadIdx.x;
    const int wid  = t >> 5;
    const int lane = t & 31;
    const int grp  = lane >> 2;
    const int tig  = lane & 3;
    const int wm   = (wid >> 2) * 64;
    const int wn   = (wid & 3) * 32;
    const int m0   = blockIdx.y * 128;
    const int n0   = blockIdx.x * 128;

    const int lr = t >> 1;
    const int lc = (t & 1) * 4;

    float acc[4][4][4];
#pragma unroll
    for (int mi = 0; mi < 4; mi++)
#pragma unroll
        for (int nj = 0; nj < 4; nj++)
#pragma unroll
            for (int q = 0; q < 4; q++) acc[mi][nj][q] = 0.0f;

    const uint32_t smA0 = smem_u32(sm);

    // prologue: buffer 0
    {
        uint32_t dA = smA0;
        uint32_t dB = smA0 + TILE_F * 4;
#pragma unroll
        for (int j = 0; j < 4; j++) {
            int c = lc + j;
            cp_async16(dA + (lr * SSTR + c * 4) * 4,
                       A + (size_t)(m0 + lr) * EDIM + c * 4);
            cp_async16(dB + (lr * SSTR + c * 4) * 4,
                       W + (size_t)(n0 + lr) * EDIM + c * 4);
        }
    }
    CP_COMMIT();

    const int NIT = EDIM / BK;
    for (int it = 0; it < NIT; it++) {
        const int buf = it & 1;
        CP_WAIT(0);
        __syncthreads();   // buffer 'buf' ready AND previous compute done

        if (it + 1 < NIT) {
            const int nb = buf ^ 1;
            const int k0 = (it + 1) * BK;
            uint32_t dA = smA0 + nb * 2 * TILE_F * 4;
            uint32_t dB = dA + TILE_F * 4;
#pragma unroll
            for (int j = 0; j < 4; j++) {
                int c = lc + j;
                cp_async16(dA + (lr * SSTR + c * 4) * 4,
                           A + (size_t)(m0 + lr) * EDIM + k0 + c * 4);
                cp_async16(dB + (lr * SSTR + c * 4) * 4,
                           W + (size_t)(n0 + lr) * EDIM + k0 + c * 4);
            }
            CP_COMMIT();
        }

        const float* tA = sm + buf * 2 * TILE_F;
        const float* tB = tA + TILE_F;

#pragma unroll
        for (int ks = 0; ks < 4; ks++) {
            const int kb = ks * 8;
            uint32_t af[4][4], bf[4][2];
#pragma unroll
            for (int mi = 0; mi < 4; mi++) {
                int r = wm + mi * 16 + grp;
                af[mi][0] = __float_as_uint(tA[r * SSTR + kb + tig]);
                af[mi][1] = __float_as_uint(tA[(r + 8) * SSTR + kb + tig]);
                af[mi][2] = __float_as_uint(tA[r * SSTR + kb + tig + 4]);
                af[mi][3] = __float_as_uint(tA[(r + 8) * SSTR + kb + tig + 4]);
            }
#pragma unroll
            for (int nj = 0; nj < 4; nj++) {
                int rn = wn + nj * 8 + grp;
                bf[nj][0] = __float_as_uint(tB[rn * SSTR + kb + tig]);
                bf[nj][1] = __float_as_uint(tB[rn * SSTR + kb + tig + 4]);
            }
#pragma unroll
            for (int mi = 0; mi < 4; mi++)
#pragma unroll
                for (int nj = 0; nj < 4; nj++)
                    mma_tf32(acc[mi][nj], af[mi], bf[nj]);
        }
    }

#pragma unroll
    for (int mi = 0; mi < 4; mi++) {
        int rg = m0 + wm + mi * 16 + grp;
#pragma unroll
        for (int nj = 0; nj < 4; nj++) {
            int cg = n0 + wn + nj * 8 + tig * 2;
            float2 bv = *(const float2*)&bias[cg];
            float2 o0, o1;
            o0.x = (acc[mi][nj][0] + bv.x) * oscale;
            o0.y = (acc[mi][nj][1] + bv.y) * oscale;
            o1.x = (acc[mi][nj][2] + bv.x) * oscale;
            o1.y = (acc[mi][nj][3] + bv.y) * oscale;
            if (oround) {
                o0.x = rna_tf32(o0.x); o0.y = rna_tf32(o0.y);
                o1.x = rna_tf32(o1.x); o1.y = rna_tf32(o1.y);
            }
            *(float2*)&C[(size_t)rg * EDIM + cg]       = o0;
            *(float2*)&C[(size_t)(rg + 8) * EDIM + cg] = o1;
        }
    }
}

// ============================================================================
// Tensor-core flash attention v2: inputs pre-rounded (Q also pre-scaled).
// 64 q-rows x (b*h) per block, 256 threads (8 warps: 4M x 2N).
// cp.async double-buffered K/V; stats in registers; deferred l; 3 syncs/tile.
// smem floats: Qs 64x68, Ks 2x64x68, Vs 2x64x72 ([k][d]), Ps 64x68, red 128.
// ============================================================================
#define KPAD 68
#define VPAD 72
#define QS_F   (64 * KPAD)          // 4352
#define KS_F   (2 * 64 * KPAD)      // 8704
#define VS_F   (2 * 64 * VPAD)      // 9216
#define PS_F   (64 * KPAD)          // 4352
#define ATTN_TC_FLOATS (QS_F + KS_F + VS_F + PS_F + 128)
#define ATTN_TC_BYTES  (ATTN_TC_FLOATS * 4)

__global__ __launch_bounds__(256, 2) void attn_tc(const int* __restrict__ mask)
{
    extern __shared__ float smf[];
    float* Qs  = smf;
    float* Ks  = smf + QS_F;
    float* Vs  = smf + QS_F + KS_F;
    float* Ps  = smf + QS_F + KS_F + VS_F;
    float* red = smf + QS_F + KS_F + VS_F + PS_F;   // [64][2]

    const int t    = threadIdx.x;
    const int wid  = t >> 5;
    const int lane = t & 31;
    const int grp  = lane >> 2;
    const int tig  = lane & 3;
    const int wm   = (wid & 3) * 16;
    const int wn   = (wid >> 2) * 32;
    const int wnx  = wid >> 2;
    const int q0   = blockIdx.x * 64;
    const int bh   = blockIdx.y;
    const int b    = bh >> 4;
    const int h    = bh & 15;
    const int hofs = h * HDIM;

    const int lrow = t >> 4;       // loader row 0..15 (x4 phases -> 64)
    const int lc4  = t & 15;       // float4 col 0..15

    const uint32_t qsm = smem_u32(Qs);
    const uint32_t ksm = smem_u32(Ks);
    const uint32_t vsm = smem_u32(Vs);

    // ---- Q tile + first K/V tile via cp.async (one group) ----
#pragma unroll
    for (int p = 0; p < 4; p++) {
        int row = lrow + p * 16;
        size_t gq = (size_t)(b * TLEN + q0 + row) * EDIM + hofs + lc4 * 4;
        cp_async16(qsm + (row * KPAD + lc4 * 4) * 4, g_q + gq);
        size_t gkv = (size_t)(b * TLEN + row) * EDIM + hofs + lc4 * 4;
        cp_async16(ksm + (row * KPAD + lc4 * 4) * 4, g_k + gkv);
        cp_async16(vsm + (row * VPAD + lc4 * 4) * 4, g_v + gkv);
    }
    CP_COMMIT();

    const int r0 = wm + grp;
    const int r1 = wm + grp + 8;

    float o[4][4];
#pragma unroll
    for (int nf = 0; nf < 4; nf++)
#pragma unroll
        for (int q = 0; q < 4; q++) o[nf][q] = 0.0f;
    float mo0 = -1e30f, mo1 = -1e30f, L0 = 0.0f, L1 = 0.0f;

    for (int kt = 0; kt < TLEN / 64; kt++) {
        const int cur = kt & 1;
        CP_WAIT(0);
        __syncthreads();   // K/V[cur] (and Q on kt=0) ready; prev tile done

        if (kt + 1 < TLEN / 64) {
            const int nb = cur ^ 1;
            uint32_t kd = ksm + nb * (64 * KPAD) * 4;
            uint32_t vd = vsm + nb * (64 * VPAD) * 4;
#pragma unroll
            for (int p = 0; p < 4; p++) {
                int row = lrow + p * 16;
                size_t gkv = (size_t)(b * TLEN + (kt + 1) * 64 + row) * EDIM + hofs + lc4 * 4;
                cp_async16(kd + (row * KPAD + lc4 * 4) * 4, g_k + gkv);
                cp_async16(vd + (row * VPAD + lc4 * 4) * 4, g_v + gkv);
            }
            CP_COMMIT();
        }

        const float* tK = Ks + cur * (64 * KPAD);
        const float* tV = Vs + cur * (64 * VPAD);

        // ---- S = Q @ K^T ----
        float s[4][4];
#pragma unroll
        for (int nf = 0; nf < 4; nf++)
#pragma unroll
            for (int q = 0; q < 4; q++) s[nf][q] = 0.0f;

#pragma unroll
        for (int ks = 0; ks < 8; ks++) {
            const int kb = ks * 8;
            uint32_t af[4];
            af[0] = __float_as_uint(Qs[r0 * KPAD + kb + tig]);
            af[1] = __float_as_uint(Qs[r1 * KPAD + kb + tig]);
            af[2] = __float_as_uint(Qs[r0 * KPAD + kb + tig + 4]);
            af[3] = __float_as_uint(Qs[r1 * KPAD + kb + tig + 4]);
#pragma unroll
            for (int nf = 0; nf < 4; nf++) {
                int rn = wn + nf * 8 + grp;
                uint32_t bf[2];
                bf[0] = __float_as_uint(tK[rn * KPAD + kb + tig]);
                bf[1] = __float_as_uint(tK[rn * KPAD + kb + tig + 4]);
                mma_tf32(s[nf], af, bf);
            }
        }

        // ---- mask + warp-half max ----
        float mx0 = -1e30f, mx1 = -1e30f;
        const size_t mbase = (size_t)(b * TLEN + q0 + r0) * TLEN + kt * 64 + wn + tig * 2;
#pragma unroll
        for (int nf = 0; nf < 4; nf++) {
            int2 m0 = *(const int2*)&mask[mbase + nf * 8];
            int2 m1 = *(const int2*)&mask[mbase + (size_t)8 * TLEN + nf * 8];
            s[nf][0] = (m0.x == 0) ? -1.0e9f : s[nf][0];
            s[nf][1] = (m0.y == 0) ? -1.0e9f : s[nf][1];
            s[nf][2] = (m1.x == 0) ? -1.0e9f : s[nf][2];
            s[nf][3] = (m1.y == 0) ? -1.0e9f : s[nf][3];
            mx0 = fmaxf(mx0, fmaxf(s[nf][0], s[nf][1]));
            mx1 = fmaxf(mx1, fmaxf(s[nf][2], s[nf][3]));
        }
        mx0 = fmaxf(mx0, __shfl_xor_sync(0xffffffffu, mx0, 1));
        mx0 = fmaxf(mx0, __shfl_xor_sync(0xffffffffu, mx0, 2));
        mx1 = fmaxf(mx1, __shfl_xor_sync(0xffffffffu, mx1, 1));
        mx1 = fmaxf(mx1, __shfl_xor_sync(0xffffffffu, mx1, 2));
        if (tig == 0) {
            red[r0 * 2 + wnx] = mx0;
            red[r1 * 2 + wnx] = mx1;
        }
        __syncthreads();

        // ---- stats in registers (redundant per-thread, deterministic) ----
        float rm0 = fmaxf(red[r0 * 2], red[r0 * 2 + 1]);
        float rm1 = fmaxf(red[r1 * 2], red[r1 * 2 + 1]);
        float mN0 = fmaxf(mo0, rm0);
        float mN1 = fmaxf(mo1, rm1);
        float a0  = __expf(mo0 - mN0);
        float a1  = __expf(mo1 - mN1);
        mo0 = mN0; mo1 = mN1;

        // ---- P = exp(S - m); store tf32; local sums; rescale O ----
        float sum0 = 0.0f, sum1 = 0.0f;
#pragma unroll
        for (int nf = 0; nf < 4; nf++) {
            float p00 = __expf(s[nf][0] - mN0);
            float p01 = __expf(s[nf][1] - mN0);
            float p10 = __expf(s[nf][2] - mN1);
            float p11 = __expf(s[nf][3] - mN1);
            sum0 += p00 + p01;
            sum1 += p10 + p11;
            int col = wn + nf * 8 + tig * 2;
            *(float2*)&Ps[r0 * KPAD + col] = make_float2(rna_tf32(p00), rna_tf32(p01));
            *(float2*)&Ps[r1 * KPAD + col] = make_float2(rna_tf32(p10), rna_tf32(p11));
            o[nf][0] *= a0; o[nf][1] *= a0;
            o[nf][2] *= a1; o[nf][3] *= a1;
        }
        sum0 += __shfl_xor_sync(0xffffffffu, sum0, 1);
        sum0 += __shfl_xor_sync(0xffffffffu, sum0, 2);
        sum1 += __shfl_xor_sync(0xffffffffu, sum1, 1);
        sum1 += __shfl_xor_sync(0xffffffffu, sum1, 2);
        L0 = L0 * a0 + sum0;   // per-warp-half partial row sum (linear in alpha)
        L1 = L1 * a1 + sum1;
        __syncthreads();       // Ps visible to both warp-halves

        // ---- O += P @ V (V natural [k][d], stride 72: conflict-free) ----
#pragma unroll
        for (int ks = 0; ks < 8; ks++) {
            const int kb = ks * 8;
            uint32_t af[4];
            af[0] = __float_as_uint(Ps[r0 * KPAD + kb + tig]);
            af[1] = __float_as_uint(Ps[r1 * KPAD + kb + tig]);
            af[2] = __float_as_uint(Ps[r0 * KPAD + kb + tig + 4]);
            af[3] = __float_as_uint(Ps[r1 * KPAD + kb + tig + 4]);
#pragma unroll
            for (int nf = 0; nf < 4; nf++) {
                int n = wn + nf * 8 + grp;   // d index
                uint32_t bf[2];
                bf[0] = __float_as_uint(tV[(kb + tig) * VPAD + n]);
                bf[1] = __float_as_uint(tV[(kb + tig + 4) * VPAD + n]);
                mma_tf32(o[nf], af, bf);
            }
        }
        // no end sync: next iteration's top sync protects buffers
    }

    // ---- combine deferred l across the two warp-halves ----
    if (tig == 0) {
        red[r0 * 2 + wnx] = L0;
        red[r1 * 2 + wnx] = L1;
    }
    __syncthreads();
    const float linv0 = 1.0f / (red[r0 * 2] + red[r0 * 2 + 1]);
    const float linv1 = 1.0f / (red[r1 * 2] + red[r1 * 2 + 1]);

    const size_t orow0 = (size_t)(b * TLEN + q0 + r0) * EDIM + hofs;
    const size_t orow1 = (size_t)(b * TLEN + q0 + r1) * EDIM + hofs;
#pragma unroll
    for (int nf = 0; nf < 4; nf++) {
        int col = wn + nf * 8 + tig * 2;
        *(float2*)&g_att[orow0 + col] =
            make_float2(rna_tf32(o[nf][0] * linv0), rna_tf32(o[nf][1] * linv0));
        *(float2*)&g_att[orow1 + col] =
            make_float2(rna_tf32(o[nf][2] * linv1), rna_tf32(o[nf][3] * linv1));
    }
}

// ============================================================================
// LayerNorm over E=1024, one block (256 threads) per row.
// ============================================================================
__global__ __launch_bounds__(256) void ln_kernel(
    const float* __restrict__ X, const float* __restrict__ gam,
    const float* __restrict__ bet, float* __restrict__ out)
{
    const int row = blockIdx.x;
    const int t   = threadIdx.x;
    __shared__ float red[8];

    float4 x = *(const float4*)&X[row * EDIM + t * 4];
    float s = x.x + x.y + x.z + x.w;
#pragma unroll
    for (int ofs = 16; ofs; ofs >>= 1) s += __shfl_xor_sync(0xffffffffu, s, ofs);
    if ((t & 31) == 0) red[t >> 5] = s;
    __syncthreads();
    float tot = 0.0f;
#pragma unroll
    for (int i = 0; i < 8; i++) tot += red[i];
    float mu = tot * (1.0f / 1024.0f);

    float d0 = x.x - mu, d1 = x.y - mu, d2 = x.z - mu, d3 = x.w - mu;
    float sq = d0 * d0 + d1 * d1 + d2 * d2 + d3 * d3;
    __syncthreads();
#pragma unroll
    for (int ofs = 16; ofs; ofs >>= 1) sq += __shfl_xor_sync(0xffffffffu, sq, ofs);
    if ((t & 31) == 0) red[t >> 5] = sq;
    __syncthreads();
    float vtot = 0.0f;
#pragma unroll
    for (int i = 0; i < 8; i++) vtot += red[i];
    float inv = rsqrtf(vtot * (1.0f / 1024.0f) + 1e-5f);

    float4 g  = *(const float4*)&gam[t * 4];
    float4 be = *(const float4*)&bet[t * 4];
    float4 o4;
    o4.x = d0 * inv * g.x + be.x;
    o4.y = d1 * inv * g.y + be.y;
    o4.z = d2 * inv * g.z + be.z;
    o4.w = d3 * inv * g.w + be.w;
    *(float4*)&out[row * EDIM + t * 4] = o4;
}

// ============================================================================
extern "C" void kernel_launch(void* const* d_in, const int* in_sizes, int n_in,
                              void* d_out, int out_size)
{
    const float* query = (const float*)d_in[0];
    const float* key   = (const float*)d_in[1];
    const float* value = (const float*)d_in[2];
    const int*   mask  = (const int*)d_in[3];
    const float* Wq    = (const float*)d_in[4];
    const float* bq    = (const float*)d_in[5];
    const float* Wk    = (const float*)d_in[6];
    const float* bk    = (const float*)d_in[7];
    const float* Wv    = (const float*)d_in[8];
    const float* bv    = (const float*)d_in[9];
    const float* Wo    = (const float*)d_in[10];
    const float* bo    = (const float*)d_in[11];
    const float* gamma = (const float*)d_in[12];
    const float* beta  = (const float*)d_in[13];
    float* out = (float*)d_out;

    float *dq, *dk, *dv, *datt;
    float *rq, *rk, *rv, *rwq, *rwk, *rwv, *rwo;
    cudaGetSymbolAddress((void**)&dq,   g_q);
    cudaGetSymbolAddress((void**)&dk,   g_k);
    cudaGetSymbolAddress((void**)&dv,   g_v);
    cudaGetSymbolAddress((void**)&datt, g_att);
    cudaGetSymbolAddress((void**)&rq,   g_rq);
    cudaGetSymbolAddress((void**)&rk,   g_rk);
    cudaGetSymbolAddress((void**)&rv,   g_rv);
    cudaGetSymbolAddress((void**)&rwq,  g_rwq);
    cudaGetSymbolAddress((void**)&rwk,  g_rwk);
    cudaGetSymbolAddress((void**)&rwv,  g_rwv);
    cudaGetSymbolAddress((void**)&rwo,  g_rwo);

    cudaFuncSetAttribute(gemm_tc,
                         cudaFuncAttributeMaxDynamicSharedMemorySize, GEMM_SMEM);
    cudaFuncSetAttribute(attn_tc,
                         cudaFuncAttributeMaxDynamicSharedMemorySize, ATTN_TC_BYTES);

    const int ACT4 = (MROWS * EDIM) / 4;
    const int WT4  = (EDIM * EDIM) / 4;

    round_tf32_kernel<<<2048, 256>>>(query, rq, ACT4);
    round_tf32_kernel<<<2048, 256>>>(key,   rk, ACT4);
    round_tf32_kernel<<<2048, 256>>>(value, rv, ACT4);
    round_tf32_kernel<<<1024, 256>>>(Wq, rwq, WT4);
    round_tf32_kernel<<<1024, 256>>>(Wk, rwk, WT4);
    round_tf32_kernel<<<1024, 256>>>(Wv, rwv, WT4);
    round_tf32_kernel<<<1024, 256>>>(Wo, rwo, WT4);

    dim3 gg(EDIM / 128, MROWS / 128);   // (8, 32)

    // Q scaled by 1/8 and rounded; K/V rounded (attn consumes raw via cp.async)
    gemm_tc<<<gg, 256, GEMM_SMEM>>>(rq, rwq, bq, dq, 0.125f, 1);
    gemm_tc<<<gg, 256, GEMM_SMEM>>>(rk, rwk, bk, dk, 1.0f,   1);
    gemm_tc<<<gg, 256, GEMM_SMEM>>>(rv, rwv, bv, dv, 1.0f,   1);

    dim3 ga(TLEN / 64, BATCH * NHEAD);  // (16, 64)
    attn_tc<<<ga, 256, ATTN_TC_BYTES>>>(mask);

    // out-projection: full fp32 output (feeds LN)
    gemm_tc<<<gg, 256, GEMM_SMEM>>>(datt, rwo, bo, dq, 1.0f, 0);

    ln_kernel<<<MROWS, 256>>>(dq, gamma, beta, out);
}

// round 9
// speedup vs baseline: 2.5463x; 1.0049x over previous
#include <cuda_runtime.h>
#include <math.h>
#include <stdint.h>

#define EDIM 1024
#define TLEN 1024
#define BATCH 4
#define NHEAD 16
#define HDIM 64
#define MROWS (BATCH * TLEN)   // 4096

// ---------------- scratch (device globals: no runtime allocation) ----------
__device__ __align__(128) float g_q[(size_t)MROWS * EDIM];   // rounded, x0.125
__device__ __align__(128) float g_k[(size_t)MROWS * EDIM];   // rounded
__device__ __align__(128) float g_v[(size_t)MROWS * EDIM];   // rounded
__device__ __align__(128) float g_att[(size_t)MROWS * EDIM]; // rounded

// ============================ helpers =======================================
__device__ __forceinline__ uint32_t smem_u32(const void* p) {
    uint32_t a;
    asm("{ .reg .u64 t; cvta.to.shared.u64 t, %1; cvt.u32.u64 %0, t; }"
        : "=r"(a) : "l"(p));
    return a;
}
__device__ __forceinline__ void cp_async16(uint32_t dst, const void* src) {
    asm volatile("cp.async.cg.shared.global [%0], [%1], 16;"
                 :: "r"(dst), "l"(src));
}
#define CP_COMMIT() asm volatile("cp.async.commit_group;" ::: "memory")
#define CP_WAIT0()  asm volatile("cp.async.wait_group 0;" ::: "memory")
#define CP_WAIT1()  asm volatile("cp.async.wait_group 1;" ::: "memory")

__device__ __forceinline__ float rna_tf32(float x) {
    uint32_t u;
    asm("cvt.rna.tf32.f32 %0, %1;" : "=r"(u) : "f"(x));
    return __uint_as_float(u);
}
__device__ __forceinline__ uint32_t rna_u32(float x) {
    uint32_t u;
    asm("cvt.rna.tf32.f32 %0, %1;" : "=r"(u) : "f"(x));
    return u;
}

__device__ __forceinline__ void mma_tf32(float* d, const uint32_t* a,
                                         const uint32_t* b) {
    asm volatile(
        "mma.sync.aligned.m16n8k8.row.col.f32.tf32.tf32.f32 "
        "{%0,%1,%2,%3}, {%4,%5,%6,%7}, {%8,%9}, {%0,%1,%2,%3};"
        : "+f"(d[0]), "+f"(d[1]), "+f"(d[2]), "+f"(d[3])
        : "r"(a[0]), "r"(a[1]), "r"(a[2]), "r"(a[3]),
          "r"(b[0]), "r"(b[1]));
}

// ============================================================================
// Tensor-core tf32 GEMM: C = (A @ W^T + bias) * oscale [, rna-rounded]
// 128x128 tile, BK=32, 256 threads (8 warps: 2M x 4N), mma.m16n8k8.
// 3-stage cp.async pipeline (prefetch distance 2); fragments rna-rounded
// in-register (raw fp32 inputs accepted -> no standalone rounding passes).
// ============================================================================
#define BK 32
#define SSTR 36
#define TILE_F (128 * SSTR)
#define NSTAGE 3
#define GEMM_SMEM (NSTAGE * 2 * TILE_F * 4)   // 110592 B

__global__ __launch_bounds__(256, 2) void gemm_tc(
    const float* __restrict__ A, const float* __restrict__ W,
    const float* __restrict__ bias, float* __restrict__ C,
    float oscale, int oround)
{
    extern __shared__ float sm[];

    const int t    = threadIdx.x;
    const int wid  = t >> 5;
    const int lane = t & 31;
    const int grp  = lane >> 2;
    const int tig  = lane & 3;
    const int wm   = (wid >> 2) * 64;
    const int wn   = (wid & 3) * 32;
    const int m0   = blockIdx.y * 128;
    const int n0   = blockIdx.x * 128;

    const int lr = t >> 1;
    const int lc = (t & 1) * 4;

    float acc[4][4][4];
#pragma unroll
    for (int mi = 0; mi < 4; mi++)
#pragma unroll
        for (int nj = 0; nj < 4; nj++)
#pragma unroll
            for (int q = 0; q < 4; q++) acc[mi][nj][q] = 0.0f;

    const uint32_t smA0 = smem_u32(sm);

    // prologue: stages 0 and 1
#pragma unroll
    for (int s = 0; s < 2; s++) {
        uint32_t dA = smA0 + s * 2 * TILE_F * 4;
        uint32_t dB = dA + TILE_F * 4;
        const int k0 = s * BK;
#pragma unroll
        for (int j = 0; j < 4; j++) {
            int c = lc + j;
            cp_async16(dA + (lr * SSTR + c * 4) * 4,
                       A + (size_t)(m0 + lr) * EDIM + k0 + c * 4);
            cp_async16(dB + (lr * SSTR + c * 4) * 4,
                       W + (size_t)(n0 + lr) * EDIM + k0 + c * 4);
        }
        CP_COMMIT();
    }

    const int NIT = EDIM / BK;   // 32
    int stage = 0;
    for (int it = 0; it < NIT; it++) {
        if (it + 1 < NIT) { CP_WAIT1(); } else { CP_WAIT0(); }
        __syncthreads();   // stage 'stage' ready for all; prev compute done

        if (it + 2 < NIT) {
            int ps = stage + 2; if (ps >= NSTAGE) ps -= NSTAGE;
            const int k0 = (it + 2) * BK;
            uint32_t dA = smA0 + ps * 2 * TILE_F * 4;
            uint32_t dB = dA + TILE_F * 4;
#pragma unroll
            for (int j = 0; j < 4; j++) {
                int c = lc + j;
                cp_async16(dA + (lr * SSTR + c * 4) * 4,
                           A + (size_t)(m0 + lr) * EDIM + k0 + c * 4);
                cp_async16(dB + (lr * SSTR + c * 4) * 4,
                           W + (size_t)(n0 + lr) * EDIM + k0 + c * 4);
            }
            CP_COMMIT();
        }

        const float* tA = sm + stage * 2 * TILE_F;
        const float* tB = tA + TILE_F;

#pragma unroll
        for (int ks = 0; ks < 4; ks++) {
            const int kb = ks * 8;
            uint32_t af[4][4], bf[4][2];
#pragma unroll
            for (int mi = 0; mi < 4; mi++) {
                int r = wm + mi * 16 + grp;
                af[mi][0] = rna_u32(tA[r * SSTR + kb + tig]);
                af[mi][1] = rna_u32(tA[(r + 8) * SSTR + kb + tig]);
                af[mi][2] = rna_u32(tA[r * SSTR + kb + tig + 4]);
                af[mi][3] = rna_u32(tA[(r + 8) * SSTR + kb + tig + 4]);
            }
#pragma unroll
            for (int nj = 0; nj < 4; nj++) {
                int rn = wn + nj * 8 + grp;
                bf[nj][0] = rna_u32(tB[rn * SSTR + kb + tig]);
                bf[nj][1] = rna_u32(tB[rn * SSTR + kb + tig + 4]);
            }
#pragma unroll
            for (int mi = 0; mi < 4; mi++)
#pragma unroll
                for (int nj = 0; nj < 4; nj++)
                    mma_tf32(acc[mi][nj], af[mi], bf[nj]);
        }

        if (++stage >= NSTAGE) stage = 0;
    }

#pragma unroll
    for (int mi = 0; mi < 4; mi++) {
        int rg = m0 + wm + mi * 16 + grp;
#pragma unroll
        for (int nj = 0; nj < 4; nj++) {
            int cg = n0 + wn + nj * 8 + tig * 2;
            float2 bv = *(const float2*)&bias[cg];
            float2 o0, o1;
            o0.x = (acc[mi][nj][0] + bv.x) * oscale;
            o0.y = (acc[mi][nj][1] + bv.y) * oscale;
            o1.x = (acc[mi][nj][2] + bv.x) * oscale;
            o1.y = (acc[mi][nj][3] + bv.y) * oscale;
            if (oround) {
                o0.x = rna_tf32(o0.x); o0.y = rna_tf32(o0.y);
                o1.x = rna_tf32(o1.x); o1.y = rna_tf32(o1.y);
            }
            *(float2*)&C[(size_t)rg * EDIM + cg]       = o0;
            *(float2*)&C[(size_t)(rg + 8) * EDIM + cg] = o1;
        }
    }
}

// ============================================================================
// Tensor-core flash attention: inputs pre-rounded (Q also pre-scaled).
// 64 q-rows x (b*h) per block, 256 threads (8 warps: 4M x 2N).
// cp.async double-buffered K/V; mask LDGs hoisted above S-MMA; stats in
// registers; deferred l; 3 syncs/tile.
// ============================================================================
#define KPAD 68
#define VPAD 72
#define QS_F   (64 * KPAD)
#define KS_F   (2 * 64 * KPAD)
#define VS_F   (2 * 64 * VPAD)
#define PS_F   (64 * KPAD)
#define ATTN_TC_FLOATS (QS_F + KS_F + VS_F + PS_F + 128)
#define ATTN_TC_BYTES  (ATTN_TC_FLOATS * 4)

__global__ __launch_bounds__(256, 2) void attn_tc(const int* __restrict__ mask)
{
    extern __shared__ float smf[];
    float* Qs  = smf;
    float* Ks  = smf + QS_F;
    float* Vs  = smf + QS_F + KS_F;
    float* Ps  = smf + QS_F + KS_F + VS_F;
    float* red = smf + QS_F + KS_F + VS_F + PS_F;   // [64][2]

    const int t    = threadIdx.x;
    const int wid  = t >> 5;
    const int lane = t & 31;
    const int grp  = lane >> 2;
    const int tig  = lane & 3;
    const int wm   = (wid & 3) * 16;
    const int wn   = (wid >> 2) * 32;
    const int wnx  = wid >> 2;
    const int q0   = blockIdx.x * 64;
    const int bh   = blockIdx.y;
    const int b    = bh >> 4;
    const int h    = bh & 15;
    const int hofs = h * HDIM;

    const int lrow = t >> 4;
    const int lc4  = t & 15;

    const uint32_t qsm = smem_u32(Qs);
    const uint32_t ksm = smem_u32(Ks);
    const uint32_t vsm = smem_u32(Vs);

#pragma unroll
    for (int p = 0; p < 4; p++) {
        int row = lrow + p * 16;
        size_t gq = (size_t)(b * TLEN + q0 + row) * EDIM + hofs + lc4 * 4;
        cp_async16(qsm + (row * KPAD + lc4 * 4) * 4, g_q + gq);
        size_t gkv = (size_t)(b * TLEN + row) * EDIM + hofs + lc4 * 4;
        cp_async16(ksm + (row * KPAD + lc4 * 4) * 4, g_k + gkv);
        cp_async16(vsm + (row * VPAD + lc4 * 4) * 4, g_v + gkv);
    }
    CP_COMMIT();

    const int r0 = wm + grp;
    const int r1 = wm + grp + 8;

    float o[4][4];
#pragma unroll
    for (int nf = 0; nf < 4; nf++)
#pragma unroll
        for (int q = 0; q < 4; q++) o[nf][q] = 0.0f;
    float mo0 = -1e30f, mo1 = -1e30f, L0 = 0.0f, L1 = 0.0f;

    for (int kt = 0; kt < TLEN / 64; kt++) {
        const int cur = kt & 1;
        CP_WAIT0();
        __syncthreads();

        if (kt + 1 < TLEN / 64) {
            const int nb = cur ^ 1;
            uint32_t kd = ksm + nb * (64 * KPAD) * 4;
            uint32_t vd = vsm + nb * (64 * VPAD) * 4;
#pragma unroll
            for (int p = 0; p < 4; p++) {
                int row = lrow + p * 16;
                size_t gkv = (size_t)(b * TLEN + (kt + 1) * 64 + row) * EDIM + hofs + lc4 * 4;
                cp_async16(kd + (row * KPAD + lc4 * 4) * 4, g_k + gkv);
                cp_async16(vd + (row * VPAD + lc4 * 4) * 4, g_v + gkv);
            }
            CP_COMMIT();
        }

        // ---- hoisted mask loads (overlap long-scoreboard with MMAs) ----
        int2 mreg0[4], mreg1[4];
        const size_t mbase = (size_t)(b * TLEN + q0 + r0) * TLEN + kt * 64 + wn + tig * 2;
#pragma unroll
        for (int nf = 0; nf < 4; nf++) {
            mreg0[nf] = *(const int2*)&mask[mbase + nf * 8];
            mreg1[nf] = *(const int2*)&mask[mbase + (size_t)8 * TLEN + nf * 8];
        }

        const float* tK = Ks + cur * (64 * KPAD);
        const float* tV = Vs + cur * (64 * VPAD);

        // ---- S = Q @ K^T ----
        float s[4][4];
#pragma unroll
        for (int nf = 0; nf < 4; nf++)
#pragma unroll
            for (int q = 0; q < 4; q++) s[nf][q] = 0.0f;

#pragma unroll
        for (int ks = 0; ks < 8; ks++) {
            const int kb = ks * 8;
            uint32_t af[4];
            af[0] = __float_as_uint(Qs[r0 * KPAD + kb + tig]);
            af[1] = __float_as_uint(Qs[r1 * KPAD + kb + tig]);
            af[2] = __float_as_uint(Qs[r0 * KPAD + kb + tig + 4]);
            af[3] = __float_as_uint(Qs[r1 * KPAD + kb + tig + 4]);
#pragma unroll
            for (int nf = 0; nf < 4; nf++) {
                int rn = wn + nf * 8 + grp;
                uint32_t bf[2];
                bf[0] = __float_as_uint(tK[rn * KPAD + kb + tig]);
                bf[1] = __float_as_uint(tK[rn * KPAD + kb + tig + 4]);
                mma_tf32(s[nf], af, bf);
            }
        }

        // ---- mask + warp-half max ----
        float mx0 = -1e30f, mx1 = -1e30f;
#pragma unroll
        for (int nf = 0; nf < 4; nf++) {
            s[nf][0] = (mreg0[nf].x == 0) ? -1.0e9f : s[nf][0];
            s[nf][1] = (mreg0[nf].y == 0) ? -1.0e9f : s[nf][1];
            s[nf][2] = (mreg1[nf].x == 0) ? -1.0e9f : s[nf][2];
            s[nf][3] = (mreg1[nf].y == 0) ? -1.0e9f : s[nf][3];
            mx0 = fmaxf(mx0, fmaxf(s[nf][0], s[nf][1]));
            mx1 = fmaxf(mx1, fmaxf(s[nf][2], s[nf][3]));
        }
        mx0 = fmaxf(mx0, __shfl_xor_sync(0xffffffffu, mx0, 1));
        mx0 = fmaxf(mx0, __shfl_xor_sync(0xffffffffu, mx0, 2));
        mx1 = fmaxf(mx1, __shfl_xor_sync(0xffffffffu, mx1, 1));
        mx1 = fmaxf(mx1, __shfl_xor_sync(0xffffffffu, mx1, 2));
        if (tig == 0) {
            red[r0 * 2 + wnx] = mx0;
            red[r1 * 2 + wnx] = mx1;
        }
        __syncthreads();

        float rm0 = fmaxf(red[r0 * 2], red[r0 * 2 + 1]);
        float rm1 = fmaxf(red[r1 * 2], red[r1 * 2 + 1]);
        float mN0 = fmaxf(mo0, rm0);
        float mN1 = fmaxf(mo1, rm1);
        float a0  = __expf(mo0 - mN0);
        float a1  = __expf(mo1 - mN1);
        mo0 = mN0; mo1 = mN1;

        float sum0 = 0.0f, sum1 = 0.0f;
#pragma unroll
        for (int nf = 0; nf < 4; nf++) {
            float p00 = __expf(s[nf][0] - mN0);
            float p01 = __expf(s[nf][1] - mN0);
            float p10 = __expf(s[nf][2] - mN1);
            float p11 = __expf(s[nf][3] - mN1);
            sum0 += p00 + p01;
            sum1 += p10 + p11;
            int col = wn + nf * 8 + tig * 2;
            *(float2*)&Ps[r0 * KPAD + col] = make_float2(rna_tf32(p00), rna_tf32(p01));
            *(float2*)&Ps[r1 * KPAD + col] = make_float2(rna_tf32(p10), rna_tf32(p11));
            o[nf][0] *= a0; o[nf][1] *= a0;
            o[nf][2] *= a1; o[nf][3] *= a1;
        }
        sum0 += __shfl_xor_sync(0xffffffffu, sum0, 1);
        sum0 += __shfl_xor_sync(0xffffffffu, sum0, 2);
        sum1 += __shfl_xor_sync(0xffffffffu, sum1, 1);
        sum1 += __shfl_xor_sync(0xffffffffu, sum1, 2);
        L0 = L0 * a0 + sum0;
        L1 = L1 * a1 + sum1;
        __syncthreads();

        // ---- O += P @ V ----
#pragma unroll
        for (int ks = 0; ks < 8; ks++) {
            const int kb = ks * 8;
            uint32_t af[4];
            af[0] = __float_as_uint(Ps[r0 * KPAD + kb + tig]);
            af[1] = __float_as_uint(Ps[r1 * KPAD + kb + tig]);
            af[2] = __float_as_uint(Ps[r0 * KPAD + kb + tig + 4]);
            af[3] = __float_as_uint(Ps[r1 * KPAD + kb + tig + 4]);
#pragma unroll
            for (int nf = 0; nf < 4; nf++) {
                int n = wn + nf * 8 + grp;
                uint32_t bf[2];
                bf[0] = __float_as_uint(tV[(kb + tig) * VPAD + n]);
                bf[1] = __float_as_uint(tV[(kb + tig + 4) * VPAD + n]);
                mma_tf32(o[nf], af, bf);
            }
        }
    }

    if (tig == 0) {
        red[r0 * 2 + wnx] = L0;
        red[r1 * 2 + wnx] = L1;
    }
    __syncthreads();
    const float linv0 = 1.0f / (red[r0 * 2] + red[r0 * 2 + 1]);
    const float linv1 = 1.0f / (red[r1 * 2] + red[r1 * 2 + 1]);

    const size_t orow0 = (size_t)(b * TLEN + q0 + r0) * EDIM + hofs;
    const size_t orow1 = (size_t)(b * TLEN + q0 + r1) * EDIM + hofs;
#pragma unroll
    for (int nf = 0; nf < 4; nf++) {
        int col = wn + nf * 8 + tig * 2;
        *(float2*)&g_att[orow0 + col] =
            make_float2(rna_tf32(o[nf][0] * linv0), rna_tf32(o[nf][1] * linv0));
        *(float2*)&g_att[orow1 + col] =
            make_float2(rna_tf32(o[nf][2] * linv1), rna_tf32(o[nf][3] * linv1));
    }
}

// ============================================================================
// LayerNorm over E=1024, one block (256 threads) per row.
// ============================================================================
__global__ __launch_bounds__(256) void ln_kernel(
    const float* __restrict__ X, const float* __restrict__ gam,
    const float* __restrict__ bet, float* __restrict__ out)
{
    const int row = blockIdx.x;
    const int t   = threadIdx.x;
    __shared__ float red[8];

    float4 x = *(const float4*)&X[row * EDIM + t * 4];
    float s = x.x + x.y + x.z + x.w;
#pragma unroll
    for (int ofs = 16; ofs; ofs >>= 1) s += __shfl_xor_sync(0xffffffffu, s, ofs);
    if ((t & 31) == 0) red[t >> 5] = s;
    __syncthreads();
    float tot = 0.0f;
#pragma unroll
    for (int i = 0; i < 8; i++) tot += red[i];
    float mu = tot * (1.0f / 1024.0f);

    float d0 = x.x - mu, d1 = x.y - mu, d2 = x.z - mu, d3 = x.w - mu;
    float sq = d0 * d0 + d1 * d1 + d2 * d2 + d3 * d3;
    __syncthreads();
#pragma unroll
    for (int ofs = 16; ofs; ofs >>= 1) sq += __shfl_xor_sync(0xffffffffu, sq, ofs);
    if ((t & 31) == 0) red[t >> 5] = sq;
    __syncthreads();
    float vtot = 0.0f;
#pragma unroll
    for (int i = 0; i < 8; i++) vtot += red[i];
    float inv = rsqrtf(vtot * (1.0f / 1024.0f) + 1e-5f);

    float4 g  = *(const float4*)&gam[t * 4];
    float4 be = *(const float4*)&bet[t * 4];
    float4 o4;
    o4.x = d0 * inv * g.x + be.x;
    o4.y = d1 * inv * g.y + be.y;
    o4.z = d2 * inv * g.z + be.z;
    o4.w = d3 * inv * g.w + be.w;
    *(float4*)&out[row * EDIM + t * 4] = o4;
}

// ============================================================================
extern "C" void kernel_launch(void* const* d_in, const int* in_sizes, int n_in,
                              void* d_out, int out_size)
{
    const float* query = (const float*)d_in[0];
    const float* key   = (const float*)d_in[1];
    const float* value = (const float*)d_in[2];
    const int*   mask  = (const int*)d_in[3];
    const float* Wq    = (const float*)d_in[4];
    const float* bq    = (const float*)d_in[5];
    const float* Wk    = (const float*)d_in[6];
    const float* bk    = (const float*)d_in[7];
    const float* Wv    = (const float*)d_in[8];
    const float* bv    = (const float*)d_in[9];
    const float* Wo    = (const float*)d_in[10];
    const float* bo    = (const float*)d_in[11];
    const float* gamma = (const float*)d_in[12];
    const float* beta  = (const float*)d_in[13];
    float* out = (float*)d_out;

    float *dq, *dk, *dv, *datt;
    cudaGetSymbolAddress((void**)&dq,   g_q);
    cudaGetSymbolAddress((void**)&dk,   g_k);
    cudaGetSymbolAddress((void**)&dv,   g_v);
    cudaGetSymbolAddress((void**)&datt, g_att);

    cudaFuncSetAttribute(gemm_tc,
                         cudaFuncAttributeMaxDynamicSharedMemorySize, GEMM_SMEM);
    cudaFuncSetAttribute(attn_tc,
                         cudaFuncAttributeMaxDynamicSharedMemorySize, ATTN_TC_BYTES);

    dim3 gg(EDIM / 128, MROWS / 128);   // (8, 32)

    // Raw inputs; fragments rounded in-register. Q scaled 1/8 + rounded out.
    gemm_tc<<<gg, 256, GEMM_SMEM>>>(query, Wq, bq, dq, 0.125f, 1);
    gemm_tc<<<gg, 256, GEMM_SMEM>>>(key,   Wk, bk, dk, 1.0f,   1);
    gemm_tc<<<gg, 256, GEMM_SMEM>>>(value, Wv, bv, dv, 1.0f,   1);

    dim3 ga(TLEN / 64, BATCH * NHEAD);  // (16, 64)
    attn_tc<<<ga, 256, ATTN_TC_BYTES>>>(mask);

    gemm_tc<<<gg, 256, GEMM_SMEM>>>(datt, Wo, bo, dq, 1.0f, 0);

    ln_kernel<<<MROWS, 256>>>(dq, gamma, beta, out);
}

// round 10
// speedup vs baseline: 4.3803x; 1.7203x over previous
#include <cuda_runtime.h>
#include <cuda_fp16.h>
#include <math.h>
#include <stdint.h>

#define EDIM 1024
#define TLEN 1024
#define BATCH 4
#define NHEAD 16
#define HDIM 64
#define MROWS (BATCH * TLEN)   // 4096

// ---------------- scratch (device globals: no runtime allocation) ----------
__device__ __align__(128) __half g_hx[3][(size_t)MROWS * EDIM]; // q,k,v inputs fp16
__device__ __align__(128) __half g_hw[4][(size_t)EDIM * EDIM];  // Wq,Wk,Wv,Wo fp16
__device__ __align__(128) __half g_qh[(size_t)MROWS * EDIM];    // Q proj (x0.125)
__device__ __align__(128) __half g_kh[(size_t)MROWS * EDIM];
__device__ __align__(128) __half g_vh[(size_t)MROWS * EDIM];
__device__ __align__(128) __half g_atth[(size_t)MROWS * EDIM];
__device__ __align__(128) float  g_o[(size_t)MROWS * EDIM];

// ============================ helpers =======================================
__device__ __forceinline__ uint32_t smem_u32(const void* p) {
    uint32_t a;
    asm("{ .reg .u64 t; cvta.to.shared.u64 t, %1; cvt.u32.u64 %0, t; }"
        : "=r"(a) : "l"(p));
    return a;
}
__device__ __forceinline__ void cp_async16(uint32_t dst, const void* src) {
    asm volatile("cp.async.cg.shared.global [%0], [%1], 16;"
                 :: "r"(dst), "l"(src));
}
#define CP_COMMIT() asm volatile("cp.async.commit_group;" ::: "memory")
#define CP_WAIT0()  asm volatile("cp.async.wait_group 0;" ::: "memory")
#define CP_WAIT1()  asm volatile("cp.async.wait_group 1;" ::: "memory")

__device__ __forceinline__ void mma_f16(float* d, const uint32_t* a,
                                        const uint32_t* b) {
    asm volatile(
        "mma.sync.aligned.m16n8k16.row.col.f32.f16.f16.f32 "
        "{%0,%1,%2,%3}, {%4,%5,%6,%7}, {%8,%9}, {%0,%1,%2,%3};"
        : "+f"(d[0]), "+f"(d[1]), "+f"(d[2]), "+f"(d[3])
        : "r"(a[0]), "r"(a[1]), "r"(a[2]), "r"(a[3]),
          "r"(b[0]), "r"(b[1]));
}
__device__ __forceinline__ void ldsm_x4(uint32_t* r, uint32_t addr) {
    asm volatile("ldmatrix.sync.aligned.m8n8.x4.shared.b16 {%0,%1,%2,%3}, [%4];"
                 : "=r"(r[0]), "=r"(r[1]), "=r"(r[2]), "=r"(r[3]) : "r"(addr));
}
__device__ __forceinline__ void ldsm_x2(uint32_t* r, uint32_t addr) {
    asm volatile("ldmatrix.sync.aligned.m8n8.x2.shared.b16 {%0,%1}, [%2];"
                 : "=r"(r[0]), "=r"(r[1]) : "r"(addr));
}
__device__ __forceinline__ void ldsm_x2_t(uint32_t* r, uint32_t addr) {
    asm volatile("ldmatrix.sync.aligned.m8n8.x2.trans.shared.b16 {%0,%1}, [%2];"
                 : "=r"(r[0]), "=r"(r[1]) : "r"(addr));
}

// ============================================================================
// Batched fp32 -> fp16 convert: z in [0,7): 3 activations + 4 weights.
// ============================================================================
struct CvtArgs { const float* x[7]; __half* y[7]; };

__global__ __launch_bounds__(256) void cvt7_kernel(CvtArgs args)
{
    const int z  = blockIdx.y;
    const int n4 = (z < 3) ? (MROWS * EDIM / 4) : (EDIM * EDIM / 4);
    const float* x = args.x[z];
    __half* y = args.y[z];
    int i = blockIdx.x * blockDim.x + threadIdx.x;
    const int stride = gridDim.x * blockDim.x;
    for (; i < n4; i += stride) {
        float4 v = *(const float4*)&x[i * 4];
        __half2 h0 = __floats2half2_rn(v.x, v.y);
        __half2 h1 = __floats2half2_rn(v.z, v.w);
        uint2 o = make_uint2(*(uint32_t*)&h0, *(uint32_t*)&h1);
        *(uint2*)&y[i * 4] = o;
    }
}

// ============================================================================
// fp16 tensor-core GEMM: C = (A @ W^T + bias) * oscale
// A fp16 [M][1024], W fp16 [N][1024]. Out fp32 (Ch==null) or fp16 (Ch).
// 128x128 tile, BK=64, 3-stage cp.async, 8 warps 2Mx4N, ldmatrix fragments.
// ============================================================================
#define HSTR 72                       // halfs per smem row (64 data + 8 pad)
#define HTILEB (128 * HSTR * 2)       // bytes per operand tile = 18432
#define GEMMH_SMEM (3 * 2 * HTILEB)   // 110592

__global__ __launch_bounds__(256, 2) void gemm_h(
    const __half* __restrict__ A, const __half* __restrict__ W,
    const float* __restrict__ bias, float* __restrict__ Cf,
    __half* __restrict__ Ch, float oscale)
{
    extern __shared__ char smraw[];
    const uint32_t sm0 = smem_u32(smraw);

    const int t    = threadIdx.x;
    const int wid  = t >> 5;
    const int lane = t & 31;
    const int grp  = lane >> 2;
    const int tig  = lane & 3;
    const int wm   = (wid >> 2) * 64;
    const int wn   = (wid & 3) * 32;
    const int m0   = blockIdx.y * 128;
    const int n0   = blockIdx.x * 128;

    const int lr = t >> 1;            // loader row 0..127
    const int cc = (t & 1) * 4;       // first 16B chunk

    const int laRow = lane & 15, laCol = (lane >> 4) * 8;
    const int lbRow = lane & 7,  lbCol = ((lane >> 3) & 1) * 8;

    float acc[4][4][4];
#pragma unroll
    for (int mi = 0; mi < 4; mi++)
#pragma unroll
        for (int nj = 0; nj < 4; nj++)
#pragma unroll
            for (int q = 0; q < 4; q++) acc[mi][nj][q] = 0.0f;

    // prologue: stages 0,1
#pragma unroll
    for (int s = 0; s < 2; s++) {
        uint32_t dA = sm0 + s * 2 * HTILEB;
        uint32_t dB = dA + HTILEB;
        const int k0 = s * 64;
#pragma unroll
        for (int j = 0; j < 4; j++) {
            int c = cc + j;
            cp_async16(dA + (lr * HSTR + c * 8) * 2,
                       A + (size_t)(m0 + lr) * EDIM + k0 + c * 8);
            cp_async16(dB + (lr * HSTR + c * 8) * 2,
                       W + (size_t)(n0 + lr) * EDIM + k0 + c * 8);
        }
        CP_COMMIT();
    }

    const int NIT = EDIM / 64;   // 16
    int stage = 0;
    for (int it = 0; it < NIT; it++) {
        if (it + 1 < NIT) { CP_WAIT1(); } else { CP_WAIT0(); }
        __syncthreads();

        if (it + 2 < NIT) {
            int ps = stage + 2; if (ps >= 3) ps -= 3;
            const int k0 = (it + 2) * 64;
            uint32_t dA = sm0 + ps * 2 * HTILEB;
            uint32_t dB = dA + HTILEB;
#pragma unroll
            for (int j = 0; j < 4; j++) {
                int c = cc + j;
                cp_async16(dA + (lr * HSTR + c * 8) * 2,
                           A + (size_t)(m0 + lr) * EDIM + k0 + c * 8);
                cp_async16(dB + (lr * HSTR + c * 8) * 2,
                           W + (size_t)(n0 + lr) * EDIM + k0 + c * 8);
            }
            CP_COMMIT();
        }

        const uint32_t aS = sm0 + stage * 2 * HTILEB;
        const uint32_t bS = aS + HTILEB;

#pragma unroll
        for (int ks = 0; ks < 4; ks++) {
            uint32_t af[4][4], bf[4][2];
#pragma unroll
            for (int mi = 0; mi < 4; mi++)
                ldsm_x4(af[mi], aS + ((wm + mi * 16 + laRow) * HSTR
                                      + ks * 16 + laCol) * 2);
#pragma unroll
            for (int nj = 0; nj < 4; nj++)
                ldsm_x2(bf[nj], bS + ((wn + nj * 8 + lbRow) * HSTR
                                      + ks * 16 + lbCol) * 2);
#pragma unroll
            for (int mi = 0; mi < 4; mi++)
#pragma unroll
                for (int nj = 0; nj < 4; nj++)
                    mma_f16(acc[mi][nj], af[mi], bf[nj]);
        }

        if (++stage >= 3) stage = 0;
    }

#pragma unroll
    for (int mi = 0; mi < 4; mi++) {
        int rg = m0 + wm + mi * 16 + grp;
#pragma unroll
        for (int nj = 0; nj < 4; nj++) {
            int cg = n0 + wn + nj * 8 + tig * 2;
            float2 bv = *(const float2*)&bias[cg];
            float o00 = (acc[mi][nj][0] + bv.x) * oscale;
            float o01 = (acc[mi][nj][1] + bv.y) * oscale;
            float o10 = (acc[mi][nj][2] + bv.x) * oscale;
            float o11 = (acc[mi][nj][3] + bv.y) * oscale;
            if (Ch) {
                __half2 h0 = __floats2half2_rn(o00, o01);
                __half2 h1 = __floats2half2_rn(o10, o11);
                *(__half2*)&Ch[(size_t)rg * EDIM + cg]       = h0;
                *(__half2*)&Ch[(size_t)(rg + 8) * EDIM + cg] = h1;
            } else {
                *(float2*)&Cf[(size_t)rg * EDIM + cg]       = make_float2(o00, o01);
                *(float2*)&Cf[(size_t)(rg + 8) * EDIM + cg] = make_float2(o10, o11);
            }
        }
    }
}

// ============================================================================
// fp16 flash attention: 64 q x (b*h) per block, 256 thr (8 warps 4M x 2N).
// S,PV on m16n8k16 fp16 via ldmatrix (V via .trans); stats exact fp32;
// cp.async double-buffered K/V; deferred l; 3 syncs/tile.
// smem (halfs): Qs 64x72 @0, Ks 2x64x72 @4608, Vs 2x64x72 @13824,
//               Ps 64x72 @23040; red float[128] @byte 55296.
// ============================================================================
#define ATTNH_SMEM (55296 + 512)

__global__ __launch_bounds__(256, 2) void attn_h(const int* __restrict__ mask)
{
    extern __shared__ char smraw[];
    __half* Ps  = (__half*)(smraw + 23040 * 2);
    float*  red = (float*)(smraw + 55296);

    const uint32_t sQ = smem_u32(smraw);
    const uint32_t sK = sQ + 4608 * 2;
    const uint32_t sV = sQ + 13824 * 2;
    const uint32_t sP = sQ + 23040 * 2;

    const int t    = threadIdx.x;
    const int wid  = t >> 5;
    const int lane = t & 31;
    const int grp  = lane >> 2;
    const int tig  = lane & 3;
    const int wm   = (wid & 3) * 16;
    const int wn   = (wid >> 2) * 32;
    const int wnx  = wid >> 2;
    const int q0   = blockIdx.x * 64;
    const int bh   = blockIdx.y;
    const int b    = bh >> 4;
    const int h    = bh & 15;
    const int hofs = h * HDIM;

    const int lrow = t >> 2;          // loader row 0..63
    const int lcc  = (t & 3) * 2;     // first chunk

    const int laRow = lane & 15, laCol = (lane >> 4) * 8;
    const int lbRow = lane & 7,  lbCol = ((lane >> 3) & 1) * 8;

    // Q + first K/V tile
#pragma unroll
    for (int j = 0; j < 2; j++) {
        int c = lcc + j;
        size_t gq = (size_t)(b * TLEN + q0 + lrow) * EDIM + hofs + c * 8;
        cp_async16(sQ + (lrow * HSTR + c * 8) * 2, g_qh + gq);
        size_t gkv = (size_t)(b * TLEN + lrow) * EDIM + hofs + c * 8;
        cp_async16(sK + (lrow * HSTR + c * 8) * 2, g_kh + gkv);
        cp_async16(sV + (lrow * HSTR + c * 8) * 2, g_vh + gkv);
    }
    CP_COMMIT();

    const int r0 = wm + grp;
    const int r1 = wm + grp + 8;

    float o[4][4];
#pragma unroll
    for (int nf = 0; nf < 4; nf++)
#pragma unroll
        for (int q = 0; q < 4; q++) o[nf][q] = 0.0f;
    float mo0 = -1e30f, mo1 = -1e30f, L0 = 0.0f, L1 = 0.0f;

    for (int kt = 0; kt < TLEN / 64; kt++) {
        const int cur = kt & 1;
        CP_WAIT0();
        __syncthreads();

        if (kt + 1 < TLEN / 64) {
            const int nb = cur ^ 1;
            uint32_t kd = sK + nb * (64 * HSTR) * 2;
            uint32_t vd = sV + nb * (64 * HSTR) * 2;
#pragma unroll
            for (int j = 0; j < 2; j++) {
                int c = lcc + j;
                size_t gkv = (size_t)(b * TLEN + (kt + 1) * 64 + lrow) * EDIM + hofs + c * 8;
                cp_async16(kd + (lrow * HSTR + c * 8) * 2, g_kh + gkv);
                cp_async16(vd + (lrow * HSTR + c * 8) * 2, g_vh + gkv);
            }
            CP_COMMIT();
        }

        // hoisted mask loads
        int2 mreg0[4], mreg1[4];
        const size_t mbase = (size_t)(b * TLEN + q0 + r0) * TLEN + kt * 64 + wn + tig * 2;
#pragma unroll
        for (int nf = 0; nf < 4; nf++) {
            mreg0[nf] = *(const int2*)&mask[mbase + nf * 8];
            mreg1[nf] = *(const int2*)&mask[mbase + (size_t)8 * TLEN + nf * 8];
        }

        const uint32_t kB = sK + cur * (64 * HSTR) * 2;
        const uint32_t vB = sV + cur * (64 * HSTR) * 2;

        // ---- S = Q @ K^T ----
        float s[4][4];
#pragma unroll
        for (int nf = 0; nf < 4; nf++)
#pragma unroll
            for (int q = 0; q < 4; q++) s[nf][q] = 0.0f;

#pragma unroll
        for (int ks = 0; ks < 4; ks++) {
            uint32_t af[4];
            ldsm_x4(af, sQ + ((wm + laRow) * HSTR + ks * 16 + laCol) * 2);
#pragma unroll
            for (int nf = 0; nf < 4; nf++) {
                uint32_t bf[2];
                ldsm_x2(bf, kB + ((wn + nf * 8 + lbRow) * HSTR + ks * 16 + lbCol) * 2);
                mma_f16(s[nf], af, bf);
            }
        }

        // ---- mask + warp-half max ----
        float mx0 = -1e30f, mx1 = -1e30f;
#pragma unroll
        for (int nf = 0; nf < 4; nf++) {
            s[nf][0] = (mreg0[nf].x == 0) ? -1.0e9f : s[nf][0];
            s[nf][1] = (mreg0[nf].y == 0) ? -1.0e9f : s[nf][1];
            s[nf][2] = (mreg1[nf].x == 0) ? -1.0e9f : s[nf][2];
            s[nf][3] = (mreg1[nf].y == 0) ? -1.0e9f : s[nf][3];
            mx0 = fmaxf(mx0, fmaxf(s[nf][0], s[nf][1]));
            mx1 = fmaxf(mx1, fmaxf(s[nf][2], s[nf][3]));
        }
        mx0 = fmaxf(mx0, __shfl_xor_sync(0xffffffffu, mx0, 1));
        mx0 = fmaxf(mx0, __shfl_xor_sync(0xffffffffu, mx0, 2));
        mx1 = fmaxf(mx1, __shfl_xor_sync(0xffffffffu, mx1, 1));
        mx1 = fmaxf(mx1, __shfl_xor_sync(0xffffffffu, mx1, 2));
        if (tig == 0) {
            red[r0 * 2 + wnx] = mx0;
            red[r1 * 2 + wnx] = mx1;
        }
        __syncthreads();

        float rm0 = fmaxf(red[r0 * 2], red[r0 * 2 + 1]);
        float rm1 = fmaxf(red[r1 * 2], red[r1 * 2 + 1]);
        float mN0 = fmaxf(mo0, rm0);
        float mN1 = fmaxf(mo1, rm1);
        float a0  = __expf(mo0 - mN0);
        float a1  = __expf(mo1 - mN1);
        mo0 = mN0; mo1 = mN1;

        float sum0 = 0.0f, sum1 = 0.0f;
#pragma unroll
        for (int nf = 0; nf < 4; nf++) {
            float p00 = __expf(s[nf][0] - mN0);
            float p01 = __expf(s[nf][1] - mN0);
            float p10 = __expf(s[nf][2] - mN1);
            float p11 = __expf(s[nf][3] - mN1);
            sum0 += p00 + p01;
            sum1 += p10 + p11;
            int col = wn + nf * 8 + tig * 2;
            *(__half2*)&Ps[r0 * HSTR + col] = __floats2half2_rn(p00, p01);
            *(__half2*)&Ps[r1 * HSTR + col] = __floats2half2_rn(p10, p11);
            o[nf][0] *= a0; o[nf][1] *= a0;
            o[nf][2] *= a1; o[nf][3] *= a1;
        }
        sum0 += __shfl_xor_sync(0xffffffffu, sum0, 1);
        sum0 += __shfl_xor_sync(0xffffffffu, sum0, 2);
        sum1 += __shfl_xor_sync(0xffffffffu, sum1, 1);
        sum1 += __shfl_xor_sync(0xffffffffu, sum1, 2);
        L0 = L0 * a0 + sum0;
        L1 = L1 * a1 + sum1;
        __syncthreads();   // Ps visible block-wide

        // ---- O += P @ V (V [k][d] via ldmatrix.trans) ----
#pragma unroll
        for (int ks = 0; ks < 4; ks++) {
            uint32_t af[4];
            ldsm_x4(af, sP + ((wm + laRow) * HSTR + ks * 16 + laCol) * 2);
#pragma unroll
            for (int nf = 0; nf < 4; nf++) {
                uint32_t bf[2];
                ldsm_x2_t(bf, vB + ((ks * 16 + laRow) * HSTR + wn + nf * 8) * 2);
                mma_f16(o[nf], af, bf);
            }
        }
    }

    if (tig == 0) {
        red[r0 * 2 + wnx] = L0;
        red[r1 * 2 + wnx] = L1;
    }
    __syncthreads();
    const float linv0 = 1.0f / (red[r0 * 2] + red[r0 * 2 + 1]);
    const float linv1 = 1.0f / (red[r1 * 2] + red[r1 * 2 + 1]);

    const size_t orow0 = (size_t)(b * TLEN + q0 + r0) * EDIM + hofs;
    const size_t orow1 = (size_t)(b * TLEN + q0 + r1) * EDIM + hofs;
#pragma unroll
    for (int nf = 0; nf < 4; nf++) {
        int col = wn + nf * 8 + tig * 2;
        *(__half2*)&g_atth[orow0 + col] =
            __floats2half2_rn(o[nf][0] * linv0, o[nf][1] * linv0);
        *(__half2*)&g_atth[orow1 + col] =
            __floats2half2_rn(o[nf][2] * linv1, o[nf][3] * linv1);
    }
}

// ============================================================================
// LayerNorm over E=1024, one block (256 threads) per row.
// ============================================================================
__global__ __launch_bounds__(256) void ln_kernel(
    const float* __restrict__ X, const float* __restrict__ gam,
    const float* __restrict__ bet, float* __restrict__ out)
{
    const int row = blockIdx.x;
    const int t   = threadIdx.x;
    __shared__ float red[8];

    float4 x = *(const float4*)&X[row * EDIM + t * 4];
    float s = x.x + x.y + x.z + x.w;
#pragma unroll
    for (int ofs = 16; ofs; ofs >>= 1) s += __shfl_xor_sync(0xffffffffu, s, ofs);
    if ((t & 31) == 0) red[t >> 5] = s;
    __syncthreads();
    float tot = 0.0f;
#pragma unroll
    for (int i = 0; i < 8; i++) tot += red[i];
    float mu = tot * (1.0f / 1024.0f);

    float d0 = x.x - mu, d1 = x.y - mu, d2 = x.z - mu, d3 = x.w - mu;
    float sq = d0 * d0 + d1 * d1 + d2 * d2 + d3 * d3;
    __syncthreads();
#pragma unroll
    for (int ofs = 16; ofs; ofs >>= 1) sq += __shfl_xor_sync(0xffffffffu, sq, ofs);
    if ((t & 31) == 0) red[t >> 5] = sq;
    __syncthreads();
    float vtot = 0.0f;
#pragma unroll
    for (int i = 0; i < 8; i++) vtot += red[i];
    float inv = rsqrtf(vtot * (1.0f / 1024.0f) + 1e-5f);

    float4 g  = *(const float4*)&gam[t * 4];
    float4 be = *(const float4*)&bet[t * 4];
    float4 o4;
    o4.x = d0 * inv * g.x + be.x;
    o4.y = d1 * inv * g.y + be.y;
    o4.z = d2 * inv * g.z + be.z;
    o4.w = d3 * inv * g.w + be.w;
    *(float4*)&out[row * EDIM + t * 4] = o4;
}

// ============================================================================
extern "C" void kernel_launch(void* const* d_in, const int* in_sizes, int n_in,
                              void* d_out, int out_size)
{
    const float* query = (const float*)d_in[0];
    const float* key   = (const float*)d_in[1];
    const float* value = (const float*)d_in[2];
    const int*   mask  = (const int*)d_in[3];
    const float* Wq    = (const float*)d_in[4];
    const float* bq    = (const float*)d_in[5];
    const float* Wk    = (const float*)d_in[6];
    const float* bk    = (const float*)d_in[7];
    const float* Wv    = (const float*)d_in[8];
    const float* bv    = (const float*)d_in[9];
    const float* Wo    = (const float*)d_in[10];
    const float* bo    = (const float*)d_in[11];
    const float* gamma = (const float*)d_in[12];
    const float* beta  = (const float*)d_in[13];
    float* out = (float*)d_out;

    __half *hx, *hw, *qh, *kh, *vh, *atth;
    float* go;
    cudaGetSymbolAddress((void**)&hx,   g_hx);
    cudaGetSymbolAddress((void**)&hw,   g_hw);
    cudaGetSymbolAddress((void**)&qh,   g_qh);
    cudaGetSymbolAddress((void**)&kh,   g_kh);
    cudaGetSymbolAddress((void**)&vh,   g_vh);
    cudaGetSymbolAddress((void**)&atth, g_atth);
    cudaGetSymbolAddress((void**)&go,   g_o);

    const size_t ACT = (size_t)MROWS * EDIM;
    const size_t WSZ = (size_t)EDIM * EDIM;

    cudaFuncSetAttribute(gemm_h,
                         cudaFuncAttributeMaxDynamicSharedMemorySize, GEMMH_SMEM);
    cudaFuncSetAttribute(attn_h,
                         cudaFuncAttributeMaxDynamicSharedMemorySize, ATTNH_SMEM);

    // fp32 -> fp16 conversion of all GEMM operands (one batched launch)
    CvtArgs ca;
    ca.x[0] = query; ca.x[1] = key; ca.x[2] = value;
    ca.x[3] = Wq; ca.x[4] = Wk; ca.x[5] = Wv; ca.x[6] = Wo;
    ca.y[0] = hx;           ca.y[1] = hx + ACT;   ca.y[2] = hx + 2 * ACT;
    ca.y[3] = hw;           ca.y[4] = hw + WSZ;
    ca.y[5] = hw + 2 * WSZ; ca.y[6] = hw + 3 * WSZ;
    dim3 gc(1024, 7);
    cvt7_kernel<<<gc, 256>>>(ca);

    dim3 gg(EDIM / 128, MROWS / 128);   // (8, 32)

    gemm_h<<<gg, 256, GEMMH_SMEM>>>(hx,           hw,           bq, nullptr, qh, 0.125f);
    gemm_h<<<gg, 256, GEMMH_SMEM>>>(hx + ACT,     hw + WSZ,     bk, nullptr, kh, 1.0f);
    gemm_h<<<gg, 256, GEMMH_SMEM>>>(hx + 2 * ACT, hw + 2 * WSZ, bv, nullptr, vh, 1.0f);

    dim3 ga(TLEN / 64, BATCH * NHEAD);  // (16, 64)
    attn_h<<<ga, 256, ATTNH_SMEM>>>(mask);

    gemm_h<<<gg, 256, GEMMH_SMEM>>>(atth, hw + 3 * WSZ, bo, go, nullptr, 1.0f);

    ln_kernel<<<MROWS, 256>>>(go, gamma, beta, out);
}